// round 3
// baseline (speedup 1.0000x reference)
#include <cuda_runtime.h>
#include <cstdint>
#include <cstddef>

#define BB   8
#define CIN  256
#define COUT 128
#define HH   60
#define WW   80
#define OHH  120
#define OWW  160
#define HWP  (OHH*OWW)   /* 19200 plane size */

// ---------------- scratch (static device globals; no allocation) ----------------
__device__ float g_ybig[(size_t)BB * 256 * HWP]; // [b][256][120][160]: ch 0..127 = conv1 out (later a1 in place), 128..255 = shortcut conv out
__device__ float g_y11 [(size_t)BB * 128 * HWP];
__device__ float g_y2  [(size_t)BB * 128 * HWP];
__device__ float g_ssA [256];   // scale,shift interleaved for 128 ch
__device__ float g_ssSC[256];
__device__ float g_ss11[256];
__device__ float g_ss2 [256];

__device__ __forceinline__ float* pickBuf(int s) {
    return s == 0 ? g_ybig : (s == 1 ? g_y11 : g_y2);
}
__device__ __forceinline__ float* pickSS(int s) {
    return s == 0 ? g_ssA : (s == 1 ? g_ssSC : (s == 2 ? g_ss11 : g_ss2));
}

// ---------------------------------------------------------------------------
// Kernel A: fused sparse-upsample 5x5 conv for BOTH w1 and wsc (256 out ch).
// xu is zero except even (h,w) -> each 2x2 output quad at (2i,2j) uses only the
// 3x3 patch x[i-1..i+1, j-1..j+1] with a fixed tap->(offset,parity) map.
// Per thread: one quad x 16 output channels (64 accumulators).
// ---------------------------------------------------------------------------
__global__ __launch_bounds__(256, 2)
void convA_kernel(const float* __restrict__ x,
                  const float* __restrict__ w1,
                  const float* __restrict__ wsc)
{
    __shared__ float s_in[8][18][18];   // 8 cin x (16+2)^2 quad-space patch
    __shared__ float s_w [8][25][16];   // 8 cin x 25 taps x 16 out ch

    const int tid = threadIdx.x;
    const int tx = tid & 15, ty = tid >> 4;
    const int qx0 = blockIdx.x * 16;    // quad col base (0..79)
    const int qy0 = blockIdx.y * 16;    // quad row base (0..59)
    const int b     = blockIdx.z >> 4;
    const int coblk = blockIdx.z & 15;
    const int co0   = coblk * 16;       // global out channel in [0,256)
    const float* wb = (co0 < 128) ? (w1  + (size_t)co0        * CIN * 25)
                                  : (wsc + (size_t)(co0 - 128) * CIN * 25);

    float acc[2][2][16];
#pragma unroll
    for (int ph = 0; ph < 2; ph++)
#pragma unroll
        for (int pw = 0; pw < 2; pw++)
#pragma unroll
            for (int k = 0; k < 16; k++) acc[ph][pw][k] = 0.f;

    const int qi = qy0 + ty, qj = qx0 + tx;

    for (int c0 = 0; c0 < CIN; c0 += 8) {
        __syncthreads();
        // stage input patch (rows qy0-1..qy0+16, cols qx0-1..qx0+16) for 8 cin
        for (int idx = tid; idx < 8 * 18 * 18; idx += 256) {
            int cc  = idx / 324;
            int rem = idx - cc * 324;
            int r   = rem / 18, col = rem - r * 18;
            int gi = qy0 - 1 + r, gj = qx0 - 1 + col;
            float v = 0.f;
            if ((unsigned)gi < (unsigned)HH && (unsigned)gj < (unsigned)WW)
                v = x[((size_t)(b * CIN + c0 + cc) * HH + gi) * WW + gj];
            s_in[cc][r][col] = v;
        }
        // stage weights: 8 cin x 25 taps x 16 ko
        for (int idx = tid; idx < 8 * 25 * 16; idx += 256) {
            int ko  = idx & 15;
            int tap = (idx >> 4) % 25;
            int cc  = idx / 400;
            s_w[cc][tap][ko] = wb[((size_t)ko * CIN + c0 + cc) * 25 + tap];
        }
        __syncthreads();

        for (int cc = 0; cc < 8; cc++) {
            float in3[3][3];
#pragma unroll
            for (int a = 0; a < 3; a++)
#pragma unroll
                for (int d = 0; d < 3; d++) in3[a][d] = s_in[cc][ty + a][tx + d];
            // tap dh -> (input offset index E, output parity P)
            constexpr int E[5] = {0, 1, 1, 2, 2};
            constexpr int P[5] = {0, 1, 0, 1, 0};
#pragma unroll
            for (int dh = 0; dh < 5; dh++) {
#pragma unroll
                for (int dw = 0; dw < 5; dw++) {
                    const float v = in3[E[dh]][E[dw]];
                    const float* wp = &s_w[cc][dh * 5 + dw][0];
#pragma unroll
                    for (int ko = 0; ko < 16; ko++)
                        acc[P[dh]][P[dw]][ko] =
                            fmaf(v, wp[ko], acc[P[dh]][P[dw]][ko]);
                }
            }
        }
    }

    if (qi < HH) {  // qj always < 80 (5*16 exact)
#pragma unroll
        for (int ph = 0; ph < 2; ph++)
#pragma unroll
            for (int pw = 0; pw < 2; pw++) {
                const int orow = 2 * qi + ph, ocol = 2 * qj + pw;
#pragma unroll
                for (int ko = 0; ko < 16; ko++)
                    g_ybig[((size_t)(b * 256 + co0 + ko) * OHH + orow) * OWW + ocol]
                        = acc[ph][pw][ko];
            }
    }
}

// ---------------------------------------------------------------------------
// Generic 3x3 conv, pad 1, NCHW. Virtual concat: channel c < split reads inA
// (a device scratch buffer, selected by inSelA), else reads inBext (external).
// Per thread: 2x2 spatial x 16 out channels.
// ---------------------------------------------------------------------------
__global__ __launch_bounds__(256, 2)
void conv3_kernel(int inSelA, const float* __restrict__ inBext,
                  int strA, int strB, int ciTotal, int split,
                  const float* __restrict__ w, int outSel)
{
    __shared__ float s_in[4][34][34];
    __shared__ float s_w [4][9][16];

    const float* inA = pickBuf(inSelA);
    float* out = pickBuf(outSel);

    const int tid = threadIdx.x;
    const int tx = tid & 15, ty = tid >> 4;
    const int ox0 = blockIdx.x * 32;
    const int oy0 = blockIdx.y * 32;
    const int b   = blockIdx.z >> 3;
    const int co0 = (blockIdx.z & 7) * 16;

    float acc[2][2][16];
#pragma unroll
    for (int ph = 0; ph < 2; ph++)
#pragma unroll
        for (int pw = 0; pw < 2; pw++)
#pragma unroll
            for (int k = 0; k < 16; k++) acc[ph][pw][k] = 0.f;

    for (int c0 = 0; c0 < ciTotal; c0 += 4) {
        __syncthreads();
        for (int idx = tid; idx < 4 * 34 * 34; idx += 256) {
            int cc  = idx / 1156;
            int rem = idx - cc * 1156;
            int r   = rem / 34, col = rem - r * 34;
            int gi = oy0 - 1 + r, gj = ox0 - 1 + col;
            int c = c0 + cc;
            float v = 0.f;
            if ((unsigned)gi < (unsigned)OHH && (unsigned)gj < (unsigned)OWW) {
                const float* plane = (c < split)
                    ? inA   + (size_t)(b * strA + c) * HWP
                    : inBext + (size_t)(b * strB + (c - split)) * HWP;
                v = plane[gi * OWW + gj];
            }
            s_in[cc][r][col] = v;
        }
        for (int idx = tid; idx < 4 * 9 * 16; idx += 256) {
            int ko  = idx & 15;
            int tap = (idx >> 4) % 9;
            int cc  = idx / 144;
            s_w[cc][tap][ko] = w[((size_t)(co0 + ko) * ciTotal + c0 + cc) * 9 + tap];
        }
        __syncthreads();

        for (int cc = 0; cc < 4; cc++) {
            float inr[4][4];
#pragma unroll
            for (int a = 0; a < 4; a++)
#pragma unroll
                for (int d = 0; d < 4; d++)
                    inr[a][d] = s_in[cc][2 * ty + a][2 * tx + d];
#pragma unroll
            for (int kh = 0; kh < 3; kh++)
#pragma unroll
                for (int kw = 0; kw < 3; kw++) {
                    const float* wp = &s_w[cc][kh * 3 + kw][0];
#pragma unroll
                    for (int ko = 0; ko < 16; ko++) {
                        const float wv = wp[ko];
                        acc[0][0][ko] = fmaf(inr[kh    ][kw    ], wv, acc[0][0][ko]);
                        acc[0][1][ko] = fmaf(inr[kh    ][kw + 1], wv, acc[0][1][ko]);
                        acc[1][0][ko] = fmaf(inr[kh + 1][kw    ], wv, acc[1][0][ko]);
                        acc[1][1][ko] = fmaf(inr[kh + 1][kw + 1], wv, acc[1][1][ko]);
                    }
                }
        }
    }

    const int oy = oy0 + 2 * ty, ox = ox0 + 2 * tx;
#pragma unroll
    for (int ph = 0; ph < 2; ph++) {
        if (oy + ph < OHH) {
#pragma unroll
            for (int pw = 0; pw < 2; pw++)
#pragma unroll
                for (int ko = 0; ko < 16; ko++)
                    out[((size_t)(b * 128 + co0 + ko) * OHH + oy + ph) * OWW + ox + pw]
                        = acc[ph][pw][ko];
        }
    }
}

// ---------------------------------------------------------------------------
// Per-channel batch stats -> (scale, shift). One block per channel.
// Deterministic (fixed two-level tree, no atomics).
// ---------------------------------------------------------------------------
__global__ void stats_kernel(int bufSel, int bStride, int chanOff,
                             const float* __restrict__ gamma,
                             const float* __restrict__ beta,
                             int ssSel)
{
    const float* buf = pickBuf(bufSel);
    float* ss = pickSS(ssSel);
    const int c = blockIdx.x;
    const int tid = threadIdx.x;
    float s = 0.f, q = 0.f;
    for (int b = 0; b < BB; b++) {
        const float4* p = (const float4*)(buf + (size_t)(b * bStride + chanOff + c) * HWP);
        for (int i = tid; i < HWP / 4; i += 256) {
            float4 v = p[i];
            s += v.x + v.y + v.z + v.w;
            q += v.x * v.x + v.y * v.y + v.z * v.z + v.w * v.w;
        }
    }
    __shared__ float red[512];
    red[tid] = s; red[256 + tid] = q;
    __syncthreads();
    for (int off = 128; off > 0; off >>= 1) {
        if (tid < off) {
            red[tid]       += red[tid + off];
            red[256 + tid] += red[256 + tid + off];
        }
        __syncthreads();
    }
    if (tid == 0) {
        const float N = (float)(BB * HWP);
        float mean = red[0] / N;
        float var  = red[256] / N - mean * mean;
        float inv  = rsqrtf(var + 1e-5f);
        float scv  = gamma[c] * inv;
        ss[2 * c]     = scv;
        ss[2 * c + 1] = beta[c] - mean * scv;
    }
}

// In-place BN + ReLU over 128 channels of a buffer.
__global__ void bnrelu_kernel(int bufSel, int bStride, int chanOff, int ssSel)
{
    float* buf = pickBuf(bufSel);
    const float* ss = pickSS(ssSel);
    const int t  = blockIdx.x * 256 + threadIdx.x;   // 8*128*4800 float4s
    const int p  = t % 4800;
    const int bc = t / 4800;
    const int b = bc >> 7, c = bc & 127;
    const float sc = ss[2 * c], sh = ss[2 * c + 1];
    float4* ptr = (float4*)(buf + (size_t)(b * bStride + chanOff + c) * HWP) + p;
    float4 v = *ptr;
    v.x = fmaxf(fmaf(v.x, sc, sh), 0.f);
    v.y = fmaxf(fmaf(v.y, sc, sh), 0.f);
    v.z = fmaxf(fmaf(v.z, sc, sh), 0.f);
    v.w = fmaxf(fmaf(v.w, sc, sh), 0.f);
    *ptr = v;
}

// out = relu(bn(y2) + bn(ysc))
__global__ void final_kernel(float* __restrict__ out)
{
    const int t  = blockIdx.x * 256 + threadIdx.x;
    const int p  = t % 4800;
    const int bc = t / 4800;
    const int b = bc >> 7, c = bc & 127;
    const float s2  = g_ss2[2 * c],  t2  = g_ss2[2 * c + 1];
    const float ssc = g_ssSC[2 * c], tsc = g_ssSC[2 * c + 1];
    const float4 a = ((const float4*)(g_y2   + (size_t)(b * 128 + c) * HWP))[p];
    const float4 d = ((const float4*)(g_ybig + (size_t)(b * 256 + 128 + c) * HWP))[p];
    float4 o;
    o.x = fmaxf(fmaf(a.x, s2, t2) + fmaf(d.x, ssc, tsc), 0.f);
    o.y = fmaxf(fmaf(a.y, s2, t2) + fmaf(d.y, ssc, tsc), 0.f);
    o.z = fmaxf(fmaf(a.z, s2, t2) + fmaf(d.z, ssc, tsc), 0.f);
    o.w = fmaxf(fmaf(a.w, s2, t2) + fmaf(d.w, ssc, tsc), 0.f);
    ((float4*)out)[t] = o;
}

// ---------------------------------------------------------------------------
extern "C" void kernel_launch(void* const* d_in, const int* in_sizes, int n_in,
                              void* d_out, int out_size)
{
    const float* x    = (const float*)d_in[0];
    const float* side = (const float*)d_in[1];
    const float* w1   = (const float*)d_in[2];
    const float* g1   = (const float*)d_in[3];
    const float* b1   = (const float*)d_in[4];
    const float* w11  = (const float*)d_in[5];
    const float* g11  = (const float*)d_in[6];
    const float* b11  = (const float*)d_in[7];
    const float* w2   = (const float*)d_in[8];
    const float* g2   = (const float*)d_in[9];
    const float* b2   = (const float*)d_in[10];
    const float* wsc  = (const float*)d_in[11];
    const float* gsc  = (const float*)d_in[12];
    const float* bsc  = (const float*)d_in[13];
    float* out = (float*)d_out;

    // 1) fused sparse 5x5 conv for w1 (ch 0..127) and wsc (ch 128..255)
    dim3 gA(5, 4, BB * 16);
    convA_kernel<<<gA, 256>>>(x, w1, wsc);

    // 2) BN stats for both halves
    stats_kernel<<<128, 256>>>(0, 256, 0,   g1,  b1,  0);
    stats_kernel<<<128, 256>>>(0, 256, 128, gsc, bsc, 1);

    // 3) a1 = relu(bn(y1)) in place (ch 0..127 of g_ybig)
    bnrelu_kernel<<<19200, 256>>>(0, 256, 0, 0);

    // 4) conv3x3 over virtual concat(a1, side) -> y11
    dim3 g3(5, 4, BB * 8);
    conv3_kernel<<<g3, 256>>>(0, side, 256, 128, 256, 128, w11, 1);

    // 5) BN stats + relu in place -> a11
    stats_kernel<<<128, 256>>>(1, 128, 0, g11, b11, 2);
    bnrelu_kernel<<<19200, 256>>>(1, 128, 0, 2);

    // 6) conv3x3 (Cin=128) -> y2
    conv3_kernel<<<g3, 256>>>(1, side, 128, 128, 128, 128, w2, 2);

    // 7) BN stats for y2; final fuse: relu(bn(y2) + bn(ysc))
    stats_kernel<<<128, 256>>>(2, 128, 0, g2, b2, 3);
    final_kernel<<<19200, 256>>>(out);
}

// round 4
// speedup vs baseline: 1.0485x; 1.0485x over previous
#include <cuda_runtime.h>
#include <cstdint>
#include <cstddef>

#define BB   8
#define CIN  256
#define COUT 128
#define HH   60
#define WW   80
#define OHH  120
#define OWW  160
#define HWP  (OHH*OWW)   /* 19200 plane size */

// ---------------- scratch (static device globals; no allocation) ----------------
__device__ float g_ybig[(size_t)BB * 256 * HWP]; // ch 0..127 = conv1 out (raw), 128..255 = shortcut conv out (raw)
__device__ float g_y11 [(size_t)BB * 128 * HWP];
__device__ float g_y2  [(size_t)BB * 128 * HWP];
__device__ float g_ssA [256];   // (scale,shift) interleaved
__device__ float g_ssSC[256];
__device__ float g_ss11[256];
__device__ float g_ss2 [256];

__device__ __forceinline__ float* pickBuf(int s) {
    return s == 0 ? g_ybig : (s == 1 ? g_y11 : g_y2);
}
__device__ __forceinline__ float* pickSS(int s) {
    return s == 0 ? g_ssA : (s == 1 ? g_ssSC : (s == 2 ? g_ss11 : g_ss2));
}

// ---------------- packed fp32x2 helpers (sm_100a FFMA2 path) ----------------
__device__ __forceinline__ unsigned long long f2_dup(float v) {
    unsigned long long r;
    asm("mov.b64 %0, {%1, %1};" : "=l"(r) : "f"(v));
    return r;
}
__device__ __forceinline__ unsigned long long ffma2(unsigned long long a,
                                                    unsigned long long b,
                                                    unsigned long long c) {
    unsigned long long d;
    asm("fma.rn.f32x2 %0, %1, %2, %3;" : "=l"(d) : "l"(a), "l"(b), "l"(c));
    return d;
}
__device__ __forceinline__ float f2_lo(unsigned long long a) {
    return __uint_as_float((unsigned)(a & 0xffffffffull));
}
__device__ __forceinline__ float f2_hi(unsigned long long a) {
    return __uint_as_float((unsigned)(a >> 32));
}

// ---------------------------------------------------------------------------
// Kernel A: fused sparse-upsample 5x5 conv for BOTH w1 and wsc (256 out ch).
// Each 2x2 output quad at (2i,2j) uses only the 3x3 patch of x with a fixed
// tap->(offset,parity) map. Per thread: one quad x 16 out ch as 8 f32x2 pairs.
// ---------------------------------------------------------------------------
__global__ __launch_bounds__(256, 2)
void convA_kernel(const float* __restrict__ x,
                  const float* __restrict__ w1,
                  const float* __restrict__ wsc)
{
    __shared__ float s_in[8][18][18];                 // 8 cin x (16+2)^2 patch
    __shared__ __align__(16) float s_w[8][25][16];    // 8 cin x 25 taps x 16 out ch

    const int tid = threadIdx.x;
    const int tx = tid & 15, ty = tid >> 4;
    const int qx0 = blockIdx.x * 16;
    const int qy0 = blockIdx.y * 16;
    const int b     = blockIdx.z >> 4;
    const int coblk = blockIdx.z & 15;
    const int co0   = coblk * 16;
    const float* wb = (co0 < 128) ? (w1  + (size_t)co0         * CIN * 25)
                                  : (wsc + (size_t)(co0 - 128) * CIN * 25);

    unsigned long long acc[2][2][8];
#pragma unroll
    for (int ph = 0; ph < 2; ph++)
#pragma unroll
        for (int pw = 0; pw < 2; pw++)
#pragma unroll
            for (int k = 0; k < 8; k++) acc[ph][pw][k] = 0ull;

    const int qi = qy0 + ty, qj = qx0 + tx;

    for (int c0 = 0; c0 < CIN; c0 += 8) {
        __syncthreads();
        for (int idx = tid; idx < 8 * 18 * 18; idx += 256) {
            int cc  = idx / 324;
            int rem = idx - cc * 324;
            int r   = rem / 18, col = rem - r * 18;
            int gi = qy0 - 1 + r, gj = qx0 - 1 + col;
            float v = 0.f;
            if ((unsigned)gi < (unsigned)HH && (unsigned)gj < (unsigned)WW)
                v = x[((size_t)(b * CIN + c0 + cc) * HH + gi) * WW + gj];
            s_in[cc][r][col] = v;
        }
        for (int idx = tid; idx < 8 * 25 * 16; idx += 256) {
            int ko  = idx & 15;
            int tap = (idx >> 4) % 25;
            int cc  = idx / 400;
            s_w[cc][tap][ko] = wb[((size_t)ko * CIN + c0 + cc) * 25 + tap];
        }
        __syncthreads();

        for (int cc = 0; cc < 8; cc++) {
            // 9 distinct input values, pre-duplicated into both f32x2 lanes
            unsigned long long in3[3][3];
#pragma unroll
            for (int a = 0; a < 3; a++)
#pragma unroll
                for (int d = 0; d < 3; d++)
                    in3[a][d] = f2_dup(s_in[cc][ty + a][tx + d]);

            constexpr int E[5] = {0, 1, 1, 2, 2};
            constexpr int P[5] = {0, 1, 0, 1, 0};
#pragma unroll
            for (int dh = 0; dh < 5; dh++) {
#pragma unroll
                for (int dw = 0; dw < 5; dw++) {
                    const unsigned long long v2 = in3[E[dh]][E[dw]];
                    const ulonglong2* wp =
                        reinterpret_cast<const ulonglong2*>(&s_w[cc][dh * 5 + dw][0]);
                    ulonglong2 wa = wp[0], wbv = wp[1], wc = wp[2], wd = wp[3];
                    unsigned long long* a = acc[P[dh]][P[dw]];
                    a[0] = ffma2(v2, wa.x,  a[0]);
                    a[1] = ffma2(v2, wa.y,  a[1]);
                    a[2] = ffma2(v2, wbv.x, a[2]);
                    a[3] = ffma2(v2, wbv.y, a[3]);
                    a[4] = ffma2(v2, wc.x,  a[4]);
                    a[5] = ffma2(v2, wc.y,  a[5]);
                    a[6] = ffma2(v2, wd.x,  a[6]);
                    a[7] = ffma2(v2, wd.y,  a[7]);
                }
            }
        }
    }

    if (qi < HH) {  // qj always < 80 (5*16 exact)
#pragma unroll
        for (int ph = 0; ph < 2; ph++)
#pragma unroll
            for (int pw = 0; pw < 2; pw++) {
                const int orow = 2 * qi + ph, ocol = 2 * qj + pw;
                float* op = &g_ybig[((size_t)(b * 256 + co0) * OHH + orow) * OWW + ocol];
#pragma unroll
                for (int p = 0; p < 8; p++) {
                    op[(size_t)(2 * p)     * HWP] = f2_lo(acc[ph][pw][p]);
                    op[(size_t)(2 * p + 1) * HWP] = f2_hi(acc[ph][pw][p]);
                }
            }
    }
}

// ---------------------------------------------------------------------------
// Generic 3x3 conv, pad 1, NCHW, f32x2-packed over 16 out channels.
// Virtual concat: channel c < split reads inA (scratch buffer) with fused
// BN(scale,shift)+ReLU applied at staging time; c >= split reads inBext raw.
// Per thread: 2x2 spatial x 16 out ch (8 f32x2 pairs each).
// ---------------------------------------------------------------------------
__global__ __launch_bounds__(256, 2)
void conv3_kernel(int inSelA, const float* __restrict__ inBext,
                  int strA, int strB, int ciTotal, int split,
                  const float* __restrict__ w, int outSel, int ssSel)
{
    __shared__ float s_in[8][34][35];                 // padded row stride 35
    __shared__ __align__(16) float s_w[8][9][16];

    const float* inA = pickBuf(inSelA);
    const float* ss  = pickSS(ssSel);
    float* out = pickBuf(outSel);

    const int tid = threadIdx.x;
    const int tx = tid & 15, ty = tid >> 4;
    const int ox0 = blockIdx.x * 32;
    const int oy0 = blockIdx.y * 32;
    const int b   = blockIdx.z >> 3;
    const int co0 = (blockIdx.z & 7) * 16;

    unsigned long long acc[2][2][8];
#pragma unroll
    for (int ph = 0; ph < 2; ph++)
#pragma unroll
        for (int pw = 0; pw < 2; pw++)
#pragma unroll
            for (int k = 0; k < 8; k++) acc[ph][pw][k] = 0ull;

    for (int c0 = 0; c0 < ciTotal; c0 += 8) {
        __syncthreads();
        for (int idx = tid; idx < 8 * 34 * 34; idx += 256) {
            int cc  = idx / 1156;
            int rem = idx - cc * 1156;
            int r   = rem / 34, col = rem - r * 34;
            int gi = oy0 - 1 + r, gj = ox0 - 1 + col;
            int c = c0 + cc;
            float v = 0.f;
            if ((unsigned)gi < (unsigned)OHH && (unsigned)gj < (unsigned)OWW) {
                if (c < split) {
                    v = inA[(size_t)(b * strA + c) * HWP + gi * OWW + gj];
                    v = fmaxf(fmaf(v, ss[2 * c], ss[2 * c + 1]), 0.f);  // fused BN+ReLU
                } else {
                    v = inBext[(size_t)(b * strB + (c - split)) * HWP + gi * OWW + gj];
                }
            }
            s_in[cc][r][col] = v;
        }
        for (int idx = tid; idx < 8 * 9 * 16; idx += 256) {
            int ko  = idx & 15;
            int tap = (idx >> 4) % 9;
            int cc  = idx / 144;
            s_w[cc][tap][ko] = w[((size_t)(co0 + ko) * ciTotal + c0 + cc) * 9 + tap];
        }
        __syncthreads();

        for (int cc = 0; cc < 8; cc++) {
            float inr[4][4];
#pragma unroll
            for (int a = 0; a < 4; a++)
#pragma unroll
                for (int d = 0; d < 4; d++)
                    inr[a][d] = s_in[cc][2 * ty + a][2 * tx + d];

#pragma unroll
            for (int kh = 0; kh < 3; kh++)
#pragma unroll
                for (int kw = 0; kw < 3; kw++) {
                    const ulonglong2* wp =
                        reinterpret_cast<const ulonglong2*>(&s_w[cc][kh * 3 + kw][0]);
                    ulonglong2 w0 = wp[0], w1v = wp[1], w2v = wp[2], w3 = wp[3];
                    unsigned long long wreg[8] = {w0.x, w0.y, w1v.x, w1v.y,
                                                  w2v.x, w2v.y, w3.x, w3.y};
                    const unsigned long long v00 = f2_dup(inr[kh    ][kw    ]);
                    const unsigned long long v01 = f2_dup(inr[kh    ][kw + 1]);
                    const unsigned long long v10 = f2_dup(inr[kh + 1][kw    ]);
                    const unsigned long long v11 = f2_dup(inr[kh + 1][kw + 1]);
#pragma unroll
                    for (int p = 0; p < 8; p++) {
                        acc[0][0][p] = ffma2(v00, wreg[p], acc[0][0][p]);
                        acc[0][1][p] = ffma2(v01, wreg[p], acc[0][1][p]);
                        acc[1][0][p] = ffma2(v10, wreg[p], acc[1][0][p]);
                        acc[1][1][p] = ffma2(v11, wreg[p], acc[1][1][p]);
                    }
                }
        }
    }

    const int oy = oy0 + 2 * ty, ox = ox0 + 2 * tx;
#pragma unroll
    for (int ph = 0; ph < 2; ph++) {
        if (oy + ph < OHH) {
#pragma unroll
            for (int pw = 0; pw < 2; pw++) {
                float* op = &out[((size_t)(b * 128 + co0) * OHH + (oy + ph)) * OWW + ox + pw];
#pragma unroll
                for (int p = 0; p < 8; p++) {
                    op[(size_t)(2 * p)     * HWP] = f2_lo(acc[ph][pw][p]);
                    op[(size_t)(2 * p + 1) * HWP] = f2_hi(acc[ph][pw][p]);
                }
            }
        }
    }
}

// ---------------------------------------------------------------------------
// Per-channel batch stats -> (scale, shift). One block per channel.
// Deterministic (fixed two-level tree, no atomics).
// ---------------------------------------------------------------------------
__global__ void stats_kernel(int bufSel, int bStride, int chanOff,
                             const float* __restrict__ gamma,
                             const float* __restrict__ beta,
                             int ssSel)
{
    const float* buf = pickBuf(bufSel);
    float* ss = pickSS(ssSel);
    const int c = blockIdx.x;
    const int tid = threadIdx.x;
    float s = 0.f, q = 0.f;
    for (int b = 0; b < BB; b++) {
        const float4* p = (const float4*)(buf + (size_t)(b * bStride + chanOff + c) * HWP);
        for (int i = tid; i < HWP / 4; i += 256) {
            float4 v = p[i];
            s += v.x + v.y + v.z + v.w;
            q += v.x * v.x + v.y * v.y + v.z * v.z + v.w * v.w;
        }
    }
    __shared__ float red[512];
    red[tid] = s; red[256 + tid] = q;
    __syncthreads();
    for (int off = 128; off > 0; off >>= 1) {
        if (tid < off) {
            red[tid]       += red[tid + off];
            red[256 + tid] += red[256 + tid + off];
        }
        __syncthreads();
    }
    if (tid == 0) {
        const float N = (float)(BB * HWP);
        float mean = red[0] / N;
        float var  = red[256] / N - mean * mean;
        float inv  = rsqrtf(var + 1e-5f);
        float scv  = gamma[c] * inv;
        ss[2 * c]     = scv;
        ss[2 * c + 1] = beta[c] - mean * scv;
    }
}

// out = relu(bn(y2) + bn(ysc))
__global__ void final_kernel(float* __restrict__ out)
{
    const int t  = blockIdx.x * 256 + threadIdx.x;
    const int p  = t % 4800;
    const int bc = t / 4800;
    const int b = bc >> 7, c = bc & 127;
    const float s2  = g_ss2[2 * c],  t2  = g_ss2[2 * c + 1];
    const float ssc = g_ssSC[2 * c], tsc = g_ssSC[2 * c + 1];
    const float4 a = ((const float4*)(g_y2   + (size_t)(b * 128 + c) * HWP))[p];
    const float4 d = ((const float4*)(g_ybig + (size_t)(b * 256 + 128 + c) * HWP))[p];
    float4 o;
    o.x = fmaxf(fmaf(a.x, s2, t2) + fmaf(d.x, ssc, tsc), 0.f);
    o.y = fmaxf(fmaf(a.y, s2, t2) + fmaf(d.y, ssc, tsc), 0.f);
    o.z = fmaxf(fmaf(a.z, s2, t2) + fmaf(d.z, ssc, tsc), 0.f);
    o.w = fmaxf(fmaf(a.w, s2, t2) + fmaf(d.w, ssc, tsc), 0.f);
    ((float4*)out)[t] = o;
}

// ---------------------------------------------------------------------------
extern "C" void kernel_launch(void* const* d_in, const int* in_sizes, int n_in,
                              void* d_out, int out_size)
{
    const float* x    = (const float*)d_in[0];
    const float* side = (const float*)d_in[1];
    const float* w1   = (const float*)d_in[2];
    const float* g1   = (const float*)d_in[3];
    const float* b1   = (const float*)d_in[4];
    const float* w11  = (const float*)d_in[5];
    const float* g11  = (const float*)d_in[6];
    const float* b11  = (const float*)d_in[7];
    const float* w2   = (const float*)d_in[8];
    const float* g2   = (const float*)d_in[9];
    const float* b2   = (const float*)d_in[10];
    const float* wsc  = (const float*)d_in[11];
    const float* gsc  = (const float*)d_in[12];
    const float* bsc  = (const float*)d_in[13];
    float* out = (float*)d_out;

    // 1) fused sparse 5x5 conv for w1 (ch 0..127) and wsc (ch 128..255) -> g_ybig raw
    dim3 gA(5, 4, BB * 16);
    convA_kernel<<<gA, 256>>>(x, w1, wsc);

    // 2) BN stats for both halves
    stats_kernel<<<128, 256>>>(0, 256, 0,   g1,  b1,  0);
    stats_kernel<<<128, 256>>>(0, 256, 128, gsc, bsc, 1);

    // 3) conv3x3 over virtual concat(relu(bn(y1)), side) -> y11 (BN+ReLU fused in staging)
    dim3 g3(5, 4, BB * 8);
    conv3_kernel<<<g3, 256>>>(0, side, 256, 128, 256, 128, w11, 1, 0);

    // 4) BN stats on y11
    stats_kernel<<<128, 256>>>(1, 128, 0, g11, b11, 2);

    // 5) conv3x3 (Cin=128) over relu(bn(y11)) -> y2 (BN+ReLU fused in staging)
    conv3_kernel<<<g3, 256>>>(1, side, 128, 128, 128, 128, w2, 2, 2);

    // 6) BN stats for y2; final fuse: relu(bn(y2) + bn(ysc))
    stats_kernel<<<128, 256>>>(2, 128, 0, g2, b2, 3);
    final_kernel<<<19200, 256>>>(out);
}

// round 7
// speedup vs baseline: 1.7480x; 1.6671x over previous
#include <cuda_runtime.h>
#include <cuda_bf16.h>
#include <cstdint>
#include <cstddef>

#define BB   8
#define CIN  256
#define HWP  (120*160)   /* 19200 output plane size */

// ---------------- scratch (static device globals; no allocation) ----------------
__device__ float g_ybig[(size_t)BB * 256 * HWP]; // ch 0..127 conv1 raw, 128..255 shortcut raw
__device__ float g_y11 [(size_t)BB * 128 * HWP];
__device__ float g_y2  [(size_t)BB * 128 * HWP];
__device__ float g_ssA [256];   // (scale,shift) interleaved
__device__ float g_ssSC[256];
__device__ float g_ss11[256];
__device__ float g_ss2 [256];

// pre-split bf16 weights: [tap][co][ci], hi + lo
__device__ __nv_bfloat16 g_wA_hi [25 * 256 * 256];
__device__ __nv_bfloat16 g_wA_lo [25 * 256 * 256];
__device__ __nv_bfloat16 g_w11_hi[ 9 * 128 * 256];
__device__ __nv_bfloat16 g_w11_lo[ 9 * 128 * 256];
__device__ __nv_bfloat16 g_w2_hi [ 9 * 128 * 128];
__device__ __nv_bfloat16 g_w2_lo [ 9 * 128 * 128];

__device__ __forceinline__ float* pickBuf(int s) {
    return s == 0 ? g_ybig : (s == 1 ? g_y11 : g_y2);
}
__device__ __forceinline__ float* pickSS(int s) {
    return s == 0 ? g_ssA : (s == 1 ? g_ssSC : (s == 2 ? g_ss11 : g_ss2));
}
__device__ __forceinline__ __nv_bfloat16* pickWhi(int s) {
    return s == 0 ? g_wA_hi : (s == 1 ? g_w11_hi : g_w2_hi);
}
__device__ __forceinline__ __nv_bfloat16* pickWlo(int s) {
    return s == 0 ? g_wA_lo : (s == 1 ? g_w11_lo : g_w2_lo);
}

// ---------------- tap tables ----------------
// set0: 3x3 conv (9 taps). sets 1-4: parity decompositions of the sparse-upsample
// 5x5 conv; parity (py,px): set1=(0,0) 9 taps, set2=(0,1) 6, set3=(1,0) 6, set4=(1,1) 4.
__constant__ int c_dy[5][9] = {
    {-1,-1,-1, 0,0,0, 1,1,1},
    {-1,-1,-1, 0,0,0, 1,1,1},
    {-1,-1, 0,0, 1,1, 0,0,0},
    { 0, 0, 0, 1,1,1, 0,0,0},
    { 0, 0, 1, 1, 0,0,0,0,0},
};
__constant__ int c_dx[5][9] = {
    {-1,0,1, -1,0,1, -1,0,1},
    {-1,0,1, -1,0,1, -1,0,1},
    { 0,1, 0,1, 0,1, 0,0,0},
    {-1,0,1, -1,0,1, 0,0,0},
    { 0,1, 0,1, 0,0,0,0,0},
};
__constant__ int c_wi[5][9] = {
    {0,1,2, 3,4,5, 6,7,8},
    {0,2,4, 10,12,14, 20,22,24},
    {1,3, 11,13, 21,23, 0,0,0},
    {5,7,9, 15,17,19, 0,0,0},
    {6,8, 16,18, 0,0,0,0,0},
};

// ---------------- PTX helpers (all plain sm_80+ — compiles at sm_100) ----------------
__device__ __forceinline__ uint32_t smem_u32(const void* p) {
    uint32_t a;
    asm("{ .reg .u64 t; cvta.to.shared.u64 t, %1; cvt.u32.u64 %0, t; }" : "=r"(a) : "l"(p));
    return a;
}
__device__ __forceinline__ void ldsm_x4(uint32_t* r, uint32_t addr) {
    asm volatile("ldmatrix.sync.aligned.m8n8.x4.shared.b16 {%0,%1,%2,%3}, [%4];"
                 : "=r"(r[0]), "=r"(r[1]), "=r"(r[2]), "=r"(r[3]) : "r"(addr));
}
__device__ __forceinline__ void mma_bf16(float* d, const uint32_t* a, const uint32_t* b) {
    asm volatile("mma.sync.aligned.m16n8k16.row.col.f32.bf16.bf16.f32 "
                 "{%0,%1,%2,%3},{%4,%5,%6,%7},{%8,%9},{%0,%1,%2,%3};"
                 : "+f"(d[0]), "+f"(d[1]), "+f"(d[2]), "+f"(d[3])
                 : "r"(a[0]), "r"(a[1]), "r"(a[2]), "r"(a[3]), "r"(b[0]), "r"(b[1]));
}

// ---------------- SMEM layout (dynamic). rows padded to 144B for conflict-free ldmatrix ----
#define OFF_SB    0                   /* int[128] */
#define OFF_SY    512
#define OFF_SX    1024
#define OFF_A_HI  2048                /* 128co x 64ci bf16, row stride 144B */
#define OFF_A_LO  (OFF_A_HI + 128*144)
#define OFF_B_HI  (OFF_A_LO + 128*144)  /* 128sp x 64ci bf16 */
#define OFF_B_LO  (OFF_B_HI + 128*144)
#define SMEM_BYTES (OFF_B_LO + 128*144) /* 75776 */

// ---------------------------------------------------------------------------
// Weight pre-split: fp32 [co][ci][taps] (optionally two 128-co halves) ->
// bf16 hi/lo [tap][co][ci].
// ---------------------------------------------------------------------------
__global__ void prep_kernel(const float* __restrict__ s0, const float* __restrict__ s1,
                            int coT, int ciT, int taps, int sel)
{
    const int idx = blockIdx.x * 256 + threadIdx.x;
    const int total = taps * coT * ciT;
    if (idx >= total) return;
    const int ci = idx % ciT;
    const int co = (idx / ciT) % coT;
    const int tap = idx / (ciT * coT);
    const float* s = s0;
    int c = co;
    if (s1 != nullptr && co >= 128) { s = s1; c = co - 128; }
    const float v = s[((size_t)c * ciT + ci) * taps + tap];
    const __nv_bfloat16 h = __float2bfloat16(v);
    const __nv_bfloat16 l = __float2bfloat16(v - __bfloat162float(h));
    pickWhi(sel)[idx] = h;
    pickWlo(sel)[idx] = l;
}

// ---------------------------------------------------------------------------
// conv-as-tap-GEMM via warp-level mma.sync (bf16 hi/lo x 3 passes, fp32 acc).
// D[128 co][128 sp] per CTA. 8 warps in 4(M)x2(N) grid, 32co x 64sp per warp.
// Virtual concat + fused BN/ReLU on first input source at staging time.
// ---------------------------------------------------------------------------
__global__ __launch_bounds__(256, 2)
void conv_mma_kernel(
    int inASel, const float* __restrict__ inAExt, const float* __restrict__ inB,
    int strA, int strB, int split, int ciTotal,
    int sH, int sW,
    int wSel, int coT,
    int tapSet, int tapCount,
    int useBn, int ssSel,
    int outSel, int outBStride,
    int oyMul, int oyAdd, int oxMul, int oxAdd,
    int outW)
{
    extern __shared__ __align__(128) char smem[];
    const uint32_t sb = smem_u32(smem);
    int* s_bt = (int*)(smem + OFF_SB);
    int* s_yt = (int*)(smem + OFF_SY);
    int* s_xt = (int*)(smem + OFF_SX);

    const int tid = threadIdx.x;
    const int lane = tid & 31, wid = tid >> 5;
    const int wm = wid >> 1, wn = wid & 1;
    const int inHW = sH * sW;
    const int outHW = HWP;

    const float* inA = (inASel < 0) ? inAExt : pickBuf(inASel);
    const float* ss  = pickSS(ssSel);
    float* outP      = pickBuf(outSel);
    const __nv_bfloat16* whi = pickWhi(wSel);
    const __nv_bfloat16* wlo = pickWlo(wSel);
    const int chanOff = blockIdx.y * 128;

    if (tid < 128) {
        const int s = blockIdx.x * 128 + tid;
        const int b = s / inHW; const int r = s - b * inHW;
        const int y = r / sW;
        s_bt[tid] = b; s_yt[tid] = y; s_xt[tid] = r - y * sW;
    }
    __syncthreads();

    // per-thread staging constants (sp fixed per thread for B staging)
    const int spT = tid & 127;
    const int cpStart = tid >> 7;          // 0 or 1
    const int bT = s_bt[spT];
    const int yT = s_yt[spT];
    const int xT = s_xt[spT];

    float acc[2][8][4];
#pragma unroll
    for (int i = 0; i < 2; i++)
#pragma unroll
        for (int j = 0; j < 8; j++)
#pragma unroll
            for (int k = 0; k < 4; k++) acc[i][j][k] = 0.f;

    // ldmatrix lane address components
    const uint32_t aRowOff = (uint32_t)(wm * 32 + (lane & 15)) * 144 + ((lane >> 4) * 16);
    const uint32_t bRowOff = (uint32_t)(wn * 64 + (lane & 7) + ((lane >> 4) << 3)) * 144
                           + (((lane >> 3) & 1) * 16);

    for (int cb = 0; cb < ciTotal; cb += 64) {
        for (int t = 0; t < tapCount; t++) {
            const int dy = c_dy[tapSet][t], dx = c_dx[tapSet][t], wi = c_wi[tapSet][t];
            __syncthreads();   // previous MMA pass done reading smem

            // ---- stage B: [128 sp][64 ci] hi/lo, packed 2-ci stores ----
            {
                const int yy = yT + dy, xx = xT + dx;
                const bool inb = ((unsigned)yy < (unsigned)sH) && ((unsigned)xx < (unsigned)sW);
                const int pix = yy * sW + xx;
                char* bh = smem + OFF_B_HI + spT * 144;
                char* bl = smem + OFF_B_LO + spT * 144;
#pragma unroll
                for (int q = 0; q < 16; q++) {
                    const int cp = cpStart + 2 * q;        // ci pair index 0..31
                    const int c = cb + 2 * cp;
                    float v0 = 0.f, v1 = 0.f;
                    if (inb) {
                        if (c < split) {
                            const float* p = inA + ((size_t)(bT * strA + c)) * inHW + pix;
                            v0 = p[0]; v1 = p[inHW];
                            if (useBn) {
                                v0 = fmaxf(fmaf(v0, ss[2*c],   ss[2*c+1]), 0.f);
                                v1 = fmaxf(fmaf(v1, ss[2*c+2], ss[2*c+3]), 0.f);
                            }
                        } else {
                            const float* p = inB + ((size_t)(bT * strB + (c - split))) * inHW + pix;
                            v0 = p[0]; v1 = p[inHW];
                        }
                    }
                    const __nv_bfloat16 h0 = __float2bfloat16(v0);
                    const __nv_bfloat16 h1 = __float2bfloat16(v1);
                    const __nv_bfloat16 l0 = __float2bfloat16(v0 - __bfloat162float(h0));
                    const __nv_bfloat16 l1 = __float2bfloat16(v1 - __bfloat162float(h1));
                    const uint32_t hp = ((uint32_t)__bfloat16_as_ushort(h1) << 16)
                                      |  (uint32_t)__bfloat16_as_ushort(h0);
                    const uint32_t lp = ((uint32_t)__bfloat16_as_ushort(l1) << 16)
                                      |  (uint32_t)__bfloat16_as_ushort(l0);
                    *(uint32_t*)(bh + cp * 4) = hp;
                    *(uint32_t*)(bl + cp * 4) = lp;
                }
            }
            // ---- stage A: [128 co][64 ci] bf16 hi/lo, 16B copies ----
            for (int idx = tid; idx < 1024; idx += 256) {
                const int c8 = idx & 7, co = idx >> 3;
                const size_t gi = ((size_t)(wi * coT + chanOff + co)) * ciTotal + cb + c8 * 8;
                const uint4 h = *(const uint4*)(whi + gi);
                const uint4 l = *(const uint4*)(wlo + gi);
                *(uint4*)(smem + OFF_A_HI + co * 144 + c8 * 16) = h;
                *(uint4*)(smem + OFF_A_LO + co * 144 + c8 * 16) = l;
            }
            __syncthreads();

            // ---- 3 MMA passes: hi*hi, hi*lo, lo*hi ----
#pragma unroll
            for (int pass = 0; pass < 3; pass++) {
                const uint32_t Abase = sb + ((pass == 2) ? OFF_A_LO : OFF_A_HI);
                const uint32_t Bbase = sb + ((pass == 1) ? OFF_B_LO : OFF_B_HI);
                const uint32_t aAddr = Abase + aRowOff;
                const uint32_t bAddr = Bbase + bRowOff;
#pragma unroll
                for (int k = 0; k < 4; k++) {
                    uint32_t a0[4], a1[4];
                    ldsm_x4(a0, aAddr + k * 32);
                    ldsm_x4(a1, aAddr + 16 * 144 + k * 32);
#pragma unroll
                    for (int tt = 0; tt < 4; tt++) {
                        uint32_t bb[4];
                        ldsm_x4(bb, bAddr + tt * (16 * 144) + k * 32);
                        mma_bf16(acc[0][tt*2  ], a0, bb);
                        mma_bf16(acc[0][tt*2+1], a0, bb + 2);
                        mma_bf16(acc[1][tt*2  ], a1, bb);
                        mma_bf16(acc[1][tt*2+1], a1, bb + 2);
                    }
                }
            }
        }
    }

    // ---- epilogue: registers -> global ----
    uint32_t off[16];
#pragma unroll
    for (int i = 0; i < 16; i++) {
        const int nf = i >> 1, e = i & 1;
        const int spi = wn * 64 + nf * 8 + (lane & 3) * 2 + e;
        const int b = s_bt[spi];
        const int oy = s_yt[spi] * oyMul + oyAdd;
        const int ox = s_xt[spi] * oxMul + oxAdd;
        off[i] = (uint32_t)(b * outBStride) * (uint32_t)outHW
               + (uint32_t)(oy * outW + ox);
    }
    const int coBase = chanOff + wm * 32 + (lane >> 2);
#pragma unroll
    for (int mi = 0; mi < 2; mi++) {
        const size_t cOff0 = (size_t)(coBase + mi * 16) * outHW;
        const size_t cOff8 = cOff0 + (size_t)8 * outHW;
#pragma unroll
        for (int nf = 0; nf < 8; nf++) {
            outP[cOff0 + off[nf*2  ]] = acc[mi][nf][0];
            outP[cOff0 + off[nf*2+1]] = acc[mi][nf][1];
            outP[cOff8 + off[nf*2  ]] = acc[mi][nf][2];
            outP[cOff8 + off[nf*2+1]] = acc[mi][nf][3];
        }
    }
}

// ---------------------------------------------------------------------------
// Per-channel batch stats -> (scale, shift). Deterministic tree reduction.
// ---------------------------------------------------------------------------
__global__ void stats_kernel(int bufSel, int bStride, int chanOff,
                             const float* __restrict__ gamma,
                             const float* __restrict__ beta,
                             int ssSel)
{
    const float* buf = pickBuf(bufSel);
    float* ss = pickSS(ssSel);
    const int c = blockIdx.x;
    const int tid = threadIdx.x;
    float s = 0.f, q = 0.f;
    for (int b = 0; b < BB; b++) {
        const float4* p = (const float4*)(buf + (size_t)(b * bStride + chanOff + c) * HWP);
        for (int i = tid; i < HWP / 4; i += 256) {
            float4 v = p[i];
            s += v.x + v.y + v.z + v.w;
            q += v.x * v.x + v.y * v.y + v.z * v.z + v.w * v.w;
        }
    }
    __shared__ float red[512];
    red[tid] = s; red[256 + tid] = q;
    __syncthreads();
    for (int off = 128; off > 0; off >>= 1) {
        if (tid < off) {
            red[tid]       += red[tid + off];
            red[256 + tid] += red[256 + tid + off];
        }
        __syncthreads();
    }
    if (tid == 0) {
        const float N = (float)(BB * HWP);
        float mean = red[0] / N;
        float var  = red[256] / N - mean * mean;
        float inv  = rsqrtf(var + 1e-5f);
        float scv  = gamma[c] * inv;
        ss[2 * c]     = scv;
        ss[2 * c + 1] = beta[c] - mean * scv;
    }
}

// out = relu(bn(y2) + bn(ysc))
__global__ void final_kernel(float* __restrict__ out)
{
    const int t  = blockIdx.x * 256 + threadIdx.x;
    const int p  = t % 4800;
    const int bc = t / 4800;
    const int b = bc >> 7, c = bc & 127;
    const float s2  = g_ss2[2 * c],  t2  = g_ss2[2 * c + 1];
    const float ssc = g_ssSC[2 * c], tsc = g_ssSC[2 * c + 1];
    const float4 a = ((const float4*)(g_y2   + (size_t)(b * 128 + c) * HWP))[p];
    const float4 d = ((const float4*)(g_ybig + (size_t)(b * 256 + 128 + c) * HWP))[p];
    float4 o;
    o.x = fmaxf(fmaf(a.x, s2, t2) + fmaf(d.x, ssc, tsc), 0.f);
    o.y = fmaxf(fmaf(a.y, s2, t2) + fmaf(d.y, ssc, tsc), 0.f);
    o.z = fmaxf(fmaf(a.z, s2, t2) + fmaf(d.z, ssc, tsc), 0.f);
    o.w = fmaxf(fmaf(a.w, s2, t2) + fmaf(d.w, ssc, tsc), 0.f);
    ((float4*)out)[t] = o;
}

// ---------------------------------------------------------------------------
extern "C" void kernel_launch(void* const* d_in, const int* in_sizes, int n_in,
                              void* d_out, int out_size)
{
    const float* x    = (const float*)d_in[0];
    const float* side = (const float*)d_in[1];
    const float* w1   = (const float*)d_in[2];
    const float* g1   = (const float*)d_in[3];
    const float* b1   = (const float*)d_in[4];
    const float* w11  = (const float*)d_in[5];
    const float* g11  = (const float*)d_in[6];
    const float* b11  = (const float*)d_in[7];
    const float* w2   = (const float*)d_in[8];
    const float* g2   = (const float*)d_in[9];
    const float* b2   = (const float*)d_in[10];
    const float* wsc  = (const float*)d_in[11];
    const float* gsc  = (const float*)d_in[12];
    const float* bsc  = (const float*)d_in[13];
    float* out = (float*)d_out;

    cudaFuncSetAttribute(conv_mma_kernel,
                         cudaFuncAttributeMaxDynamicSharedMemorySize, SMEM_BYTES);

    // 0) pre-split weights into bf16 hi/lo, [tap][co][ci]
    prep_kernel<<<(25*256*256 + 255)/256, 256>>>(w1, wsc, 256, 256, 25, 0);
    prep_kernel<<<( 9*128*256 + 255)/256, 256>>>(w11, nullptr, 128, 256, 9, 1);
    prep_kernel<<<( 9*128*128 + 255)/256, 256>>>(w2,  nullptr, 128, 128, 9, 2);

    // 1) sparse 5x5 conv (w1 -> ch 0..127, wsc -> ch 128..255 of g_ybig),
    //    4 parity launches over the 60x80 quad grid (8*4800/128 = 300 tiles).
    dim3 gA(300, 2);
    const int cnt[5] = {9, 9, 6, 6, 4};
    const int pys[5] = {0, 0, 0, 1, 1};
    const int pxs[5] = {0, 0, 1, 0, 1};
    for (int set = 1; set <= 4; set++) {
        conv_mma_kernel<<<gA, 256, SMEM_BYTES>>>(
            -1, x, nullptr, CIN, 0, CIN, CIN,
            60, 80, /*wSel*/0, /*coT*/256, set, cnt[set],
            0, 0, /*outSel*/0, 256,
            2, pys[set], 2, pxs[set], 160);
    }

    // 2) BN stats for both halves of g_ybig
    stats_kernel<<<128, 256>>>(0, 256, 0,   g1,  b1,  0);
    stats_kernel<<<128, 256>>>(0, 256, 128, gsc, bsc, 1);

    // 3) conv3x3 over virtual concat(relu(bn(y1)), side) -> y11
    dim3 g3(1200, 1);
    conv_mma_kernel<<<g3, 256, SMEM_BYTES>>>(
        0, nullptr, side, 256, 128, 128, 256,
        120, 160, /*wSel*/1, /*coT*/128, 0, 9,
        1, 0, /*outSel*/1, 128,
        1, 0, 1, 0, 160);

    // 4) BN stats on y11
    stats_kernel<<<128, 256>>>(1, 128, 0, g11, b11, 2);

    // 5) conv3x3 (Cin=128) over relu(bn(y11)) -> y2
    conv_mma_kernel<<<g3, 256, SMEM_BYTES>>>(
        1, nullptr, nullptr, 128, 0, 128, 128,
        120, 160, /*wSel*/2, /*coT*/128, 0, 9,
        1, 2, /*outSel*/2, 128,
        1, 0, 1, 0, 160);

    // 6) BN stats for y2; final fuse: relu(bn(y2) + bn(ysc))
    stats_kernel<<<128, 256>>>(2, 128, 0, g2, b2, 3);
    final_kernel<<<19200, 256>>>(out);
}

// round 9
// speedup vs baseline: 2.2002x; 1.2587x over previous
#include <cuda_runtime.h>
#include <cuda_bf16.h>
#include <cstdint>
#include <cstddef>

#define BB   8
#define CIN  256
#define HWP  (120*160)   /* 19200 output plane size */

// ---------------- scratch (static device globals; no allocation) ----------------
__device__ float g_ybig[(size_t)BB * 256 * HWP]; // ch 0..127 conv1 raw, 128..255 shortcut raw
__device__ float g_y11 [(size_t)BB * 128 * HWP];
__device__ float g_y2  [(size_t)BB * 128 * HWP];
__device__ float g_ssA [256];   // (scale,shift) interleaved
__device__ float g_ssSC[256];
__device__ float g_ss11[256];
__device__ float g_ss2 [256];

// pre-split bf16 weights: [tap][co][ci], hi + lo
__device__ __nv_bfloat16 g_wA_hi [25 * 256 * 256];
__device__ __nv_bfloat16 g_wA_lo [25 * 256 * 256];
__device__ __nv_bfloat16 g_w11_hi[ 9 * 128 * 256];
__device__ __nv_bfloat16 g_w11_lo[ 9 * 128 * 256];
__device__ __nv_bfloat16 g_w2_hi [ 9 * 128 * 128];
__device__ __nv_bfloat16 g_w2_lo [ 9 * 128 * 128];

// pre-split bf16 activations, NHWC [b][pix][c], hi + lo
__device__ __nv_bfloat16 g_xa_hi [(size_t)BB *  4800 * 256];
__device__ __nv_bfloat16 g_xa_lo [(size_t)BB *  4800 * 256];
__device__ __nv_bfloat16 g_cat_hi[(size_t)BB * 19200 * 256];
__device__ __nv_bfloat16 g_cat_lo[(size_t)BB * 19200 * 256];
__device__ __nv_bfloat16 g_a11_hi[(size_t)BB * 19200 * 128];
__device__ __nv_bfloat16 g_a11_lo[(size_t)BB * 19200 * 128];

__device__ __forceinline__ float* pickBuf(int s) {
    return s == 0 ? g_ybig : (s == 1 ? g_y11 : g_y2);
}
__device__ __forceinline__ float* pickSS(int s) {
    return s == 0 ? g_ssA : (s == 1 ? g_ssSC : (s == 2 ? g_ss11 : g_ss2));
}
__device__ __forceinline__ __nv_bfloat16* pickWhi(int s) {
    return s == 0 ? g_wA_hi : (s == 1 ? g_w11_hi : g_w2_hi);
}
__device__ __forceinline__ __nv_bfloat16* pickWlo(int s) {
    return s == 0 ? g_wA_lo : (s == 1 ? g_w11_lo : g_w2_lo);
}
__device__ __forceinline__ __nv_bfloat16* pickAhi(int s) {
    return s == 0 ? g_xa_hi : (s == 1 ? g_cat_hi : g_a11_hi);
}
__device__ __forceinline__ __nv_bfloat16* pickAlo(int s) {
    return s == 0 ? g_xa_lo : (s == 1 ? g_cat_lo : g_a11_lo);
}

// ---------------- tap tables ----------------
// set0: 3x3 conv (9 taps). sets 1-4: parity decompositions of the sparse-upsample
// 5x5 conv; parity (py,px): set1=(0,0) 9, set2=(0,1) 6, set3=(1,0) 6, set4=(1,1) 4.
__constant__ int c_dy[5][9] = {
    {-1,-1,-1, 0,0,0, 1,1,1},
    {-1,-1,-1, 0,0,0, 1,1,1},
    {-1,-1, 0,0, 1,1, 0,0,0},
    { 0, 0, 0, 1,1,1, 0,0,0},
    { 0, 0, 1, 1, 0,0,0,0,0},
};
__constant__ int c_dx[5][9] = {
    {-1,0,1, -1,0,1, -1,0,1},
    {-1,0,1, -1,0,1, -1,0,1},
    { 0,1, 0,1, 0,1, 0,0,0},
    {-1,0,1, -1,0,1, 0,0,0},
    { 0,1, 0,1, 0,0,0,0,0},
};
__constant__ int c_wi[5][9] = {
    {0,1,2, 3,4,5, 6,7,8},
    {0,2,4, 10,12,14, 20,22,24},
    {1,3, 11,13, 21,23, 0,0,0},
    {5,7,9, 15,17,19, 0,0,0},
    {6,8, 16,18, 0,0,0,0,0},
};

// ---------------- PTX helpers (sm_80+ baseline — compiles at sm_100) ----------------
__device__ __forceinline__ uint32_t smem_u32(const void* p) {
    uint32_t a;
    asm("{ .reg .u64 t; cvta.to.shared.u64 t, %1; cvt.u32.u64 %0, t; }" : "=r"(a) : "l"(p));
    return a;
}
__device__ __forceinline__ void ldsm_x4(uint32_t* r, uint32_t addr) {
    asm volatile("ldmatrix.sync.aligned.m8n8.x4.shared.b16 {%0,%1,%2,%3}, [%4];"
                 : "=r"(r[0]), "=r"(r[1]), "=r"(r[2]), "=r"(r[3]) : "r"(addr));
}
__device__ __forceinline__ void mma_bf16(float* d, const uint32_t* a, const uint32_t* b) {
    asm volatile("mma.sync.aligned.m16n8k16.row.col.f32.bf16.bf16.f32 "
                 "{%0,%1,%2,%3},{%4,%5,%6,%7},{%8,%9},{%0,%1,%2,%3};"
                 : "+f"(d[0]), "+f"(d[1]), "+f"(d[2]), "+f"(d[3])
                 : "r"(a[0]), "r"(a[1]), "r"(a[2]), "r"(a[3]), "r"(b[0]), "r"(b[1]));
}
__device__ __forceinline__ void cp16(uint32_t dst, const void* src, uint32_t sz) {
    asm volatile("cp.async.cg.shared.global [%0], [%1], 16, %2;"
                 :: "r"(dst), "l"(src), "r"(sz) : "memory");
}
__device__ __forceinline__ void cp_commit_wait() {
    asm volatile("cp.async.commit_group;" ::: "memory");
    asm volatile("cp.async.wait_group 0;" ::: "memory");
}

// ---------------- SMEM layout (dynamic), XOR-swizzled 128B rows ----------------
#define OFF_SB    0                    /* int[128] */
#define OFF_SY    512
#define OFF_SX    1024
#define OFF_A_HI  2048                 /* 128co x 64ci bf16 = 16KB each */
#define OFF_A_LO  (OFF_A_HI + 16384)
#define OFF_B_HI  (OFF_A_LO + 16384)   /* 128sp x 64ci bf16 */
#define OFF_B_LO  (OFF_B_HI + 16384)
#define SMEM_BYTES (OFF_B_LO + 16384)  /* 67584 */

// ---------------------------------------------------------------------------
// Weight pre-split: fp32 [co][ci][taps] (optionally two 128-co halves) ->
// bf16 hi/lo [tap][co][ci].
// ---------------------------------------------------------------------------
__global__ void prep_kernel(const float* __restrict__ s0, const float* __restrict__ s1,
                            int coT, int ciT, int taps, int sel)
{
    const int idx = blockIdx.x * 256 + threadIdx.x;
    const int total = taps * coT * ciT;
    if (idx >= total) return;
    const int ci = idx % ciT;
    const int co = (idx / ciT) % coT;
    const int tap = idx / (ciT * coT);
    const float* s = s0;
    int c = co;
    if (s1 != nullptr && co >= 128) { s = s1; c = co - 128; }
    const float v = s[((size_t)c * ciT + ci) * taps + tap];
    const __nv_bfloat16 h = __float2bfloat16(v);
    const __nv_bfloat16 l = __float2bfloat16(v - __bfloat162float(h));
    pickWhi(sel)[idx] = h;
    pickWlo(sel)[idx] = l;
}

// ---------------------------------------------------------------------------
// Activation pre-split: fp32 NCHW (virtual concat, optional fused BN+ReLU) ->
// bf16 hi/lo NHWC [b][pix][C]. Tile = 64 pixels x 64 channels with smem
// transpose so both reads and writes are coalesced.
// ---------------------------------------------------------------------------
__global__ __launch_bounds__(256)
void actprep_kernel(int inASel, const float* __restrict__ inAExt,
                    const float* __restrict__ inB,
                    int strA, int strB, int split, int C, int HW,
                    int useBn, int ssSel, int dstSel)
{
    __shared__ __nv_bfloat16 s_hi[64][72];
    __shared__ __nv_bfloat16 s_lo[64][72];
    const int tid = threadIdx.x;
    const int pix0 = blockIdx.x * 64;
    const int c0   = blockIdx.y * 64;
    const int b    = blockIdx.z;
    const float* inA = (inASel < 0) ? inAExt : pickBuf(inASel);
    const float* ss  = pickSS(ssSel);
    __nv_bfloat16* dhi = pickAhi(dstSel);
    __nv_bfloat16* dlo = pickAlo(dstSel);

    const int cSub = tid >> 6, pixL = tid & 63;
#pragma unroll 4
    for (int ci = 0; ci < 16; ci++) {
        const int cl = ci * 4 + cSub;
        const int c = c0 + cl;
        float v;
        if (c < split) {
            v = inA[((size_t)(b * strA + c)) * HW + pix0 + pixL];
            if (useBn) v = fmaxf(fmaf(v, ss[2 * c], ss[2 * c + 1]), 0.f);
        } else {
            v = inB[((size_t)(b * strB + (c - split))) * HW + pix0 + pixL];
        }
        const __nv_bfloat16 h = __float2bfloat16(v);
        s_hi[pixL][cl] = h;
        s_lo[pixL][cl] = __float2bfloat16(v - __bfloat162float(h));
    }
    __syncthreads();
    // write-out: 8 chunks (64 ch) x 32 pixels x 2 halves = full 64x64 tile
    const int chunk = tid & 7, pL0 = tid >> 3;
#pragma unroll
    for (int h = 0; h < 2; h++) {
        const int pL = pL0 + h * 32;
        const uint4 vh = *(const uint4*)&s_hi[pL][chunk * 8];
        const uint4 vl = *(const uint4*)&s_lo[pL][chunk * 8];
        const size_t doff = (size_t)(b * HW + pix0 + pL) * C + c0 + chunk * 8;
        *(uint4*)(dhi + doff) = vh;
        *(uint4*)(dlo + doff) = vl;
    }
}

// ---------------------------------------------------------------------------
// conv-as-tap-GEMM via mma.sync bf16 (hi/lo x 3 passes, fp32 acc).
// D[128 co][128 sp] per CTA, 8 warps 4(M)x2(N). Staging = pure cp.async 16B
// copies from pre-split NHWC activation / weight buffers; XOR-swizzled smem.
// ---------------------------------------------------------------------------
__global__ __launch_bounds__(256, 2)
void conv_mma_kernel(
    int actSel, int C, int sH, int sW,
    int wSel, int coT,
    int tapSet, int tapCount,
    int outSel, int outBStride,
    int oyMul, int oyAdd, int oxMul, int oxAdd,
    int outW)
{
    extern __shared__ __align__(128) char smem[];
    const uint32_t sb = smem_u32(smem);
    int* s_bt = (int*)(smem + OFF_SB);
    int* s_yt = (int*)(smem + OFF_SY);
    int* s_xt = (int*)(smem + OFF_SX);

    const int tid = threadIdx.x;
    const int lane = tid & 31, wid = tid >> 5;
    const int wm = wid >> 1, wn = wid & 1;
    const int inHW = sH * sW;
    const int outHW = HWP;
    const int chanOff = blockIdx.y * 128;

    float* outP = pickBuf(outSel);

    if (tid < 128) {
        const int s = blockIdx.x * 128 + tid;
        const int b = s / inHW; const int r = s - b * inHW;
        const int y = r / sW;
        s_bt[tid] = b; s_yt[tid] = y; s_xt[tid] = r - y * sW;
    }
    __syncthreads();

    // staging thread mapping: (row 0..127) x (half 0..1)
    const int rowT  = tid & 127;
    const int halfT = tid >> 7;
    const __nv_bfloat16* actSrc = halfT ? pickAlo(actSel) : pickAhi(actSel);
    const __nv_bfloat16* wSrc   = halfT ? pickWlo(wSel)   : pickWhi(wSel);
    const uint32_t bDst = sb + (halfT ? OFF_B_LO : OFF_B_HI) + rowT * 128;
    const uint32_t aDst = sb + (halfT ? OFF_A_LO : OFF_A_HI) + rowT * 128;
    const int rSwz = rowT & 7;
    const int bT = s_bt[rowT], yT = s_yt[rowT], xT = s_xt[rowT];
    const size_t wRowBase = (size_t)(chanOff + rowT) * C;   // + wi*coT*C later

    float acc[2][8][4];
#pragma unroll
    for (int i = 0; i < 2; i++)
#pragma unroll
        for (int j = 0; j < 8; j++)
#pragma unroll
            for (int k = 0; k < 4; k++) acc[i][j][k] = 0.f;

    // ldmatrix lane addressing (swizzled)
    const int sx = lane & 7;
    const uint32_t aRowBase = (uint32_t)(wm * 32 + (lane & 15)) * 128;
    const uint32_t bRowBase = (uint32_t)(wn * 64 + (lane & 7) + ((lane >> 4) << 3)) * 128;
    const int ka0 = lane >> 4;
    const int kb0 = (lane >> 3) & 1;

    for (int cb = 0; cb < C; cb += 64) {
        for (int t = 0; t < tapCount; t++) {
            const int dy = c_dy[tapSet][t], dx = c_dx[tapSet][t], wi = c_wi[tapSet][t];
            __syncthreads();   // previous MMA done reading smem

            // ---- stage B: activation row (pixel rowT shifted by tap) ----
            {
                const int yy = yT + dy, xx = xT + dx;
                const bool inb = ((unsigned)yy < (unsigned)sH) && ((unsigned)xx < (unsigned)sW);
                const __nv_bfloat16* src = inb
                    ? actSrc + (size_t)(bT * inHW + yy * sW + xx) * C + cb
                    : actSrc;
                const uint32_t sz = inb ? 16u : 0u;
#pragma unroll
                for (int c8 = 0; c8 < 8; c8++)
                    cp16(bDst + ((c8 ^ rSwz) << 4), src + c8 * 8, sz);
            }
            // ---- stage A: weight row (co = rowT) for this tap ----
            {
                const __nv_bfloat16* src = wSrc + (size_t)wi * coT * C + wRowBase + cb;
#pragma unroll
                for (int c8 = 0; c8 < 8; c8++)
                    cp16(aDst + ((c8 ^ rSwz) << 4), src + c8 * 8, 16u);
            }
            cp_commit_wait();
            __syncthreads();

            // ---- 3 MMA passes: hi*hi, hi*lo, lo*hi ----
#pragma unroll
            for (int pass = 0; pass < 3; pass++) {
                const uint32_t Abase = sb + ((pass == 2) ? OFF_A_LO : OFF_A_HI);
                const uint32_t Bbase = sb + ((pass == 1) ? OFF_B_LO : OFF_B_HI);
#pragma unroll
                for (int k = 0; k < 4; k++) {
                    const uint32_t aOff = (uint32_t)(((ka0 + 2 * k) ^ sx) << 4);
                    const uint32_t bOff = (uint32_t)(((kb0 + 2 * k) ^ sx) << 4);
                    uint32_t a0[4], a1[4];
                    ldsm_x4(a0, Abase + aRowBase + aOff);
                    ldsm_x4(a1, Abase + aRowBase + 16 * 128 + aOff);
#pragma unroll
                    for (int tt = 0; tt < 4; tt++) {
                        uint32_t bb[4];
                        ldsm_x4(bb, Bbase + bRowBase + tt * 2048 + bOff);
                        mma_bf16(acc[0][tt*2  ], a0, bb);
                        mma_bf16(acc[0][tt*2+1], a0, bb + 2);
                        mma_bf16(acc[1][tt*2  ], a1, bb);
                        mma_bf16(acc[1][tt*2+1], a1, bb + 2);
                    }
                }
            }
        }
    }

    // ---- epilogue: registers -> global (fp32 NCHW scratch) ----
    uint32_t off[16];
#pragma unroll
    for (int i = 0; i < 16; i++) {
        const int nf = i >> 1, e = i & 1;
        const int spi = wn * 64 + nf * 8 + (lane & 3) * 2 + e;
        const int b = s_bt[spi];
        const int oy = s_yt[spi] * oyMul + oyAdd;
        const int ox = s_xt[spi] * oxMul + oxAdd;
        off[i] = (uint32_t)(b * outBStride) * (uint32_t)outHW
               + (uint32_t)(oy * outW + ox);
    }
    const int coBase = chanOff + wm * 32 + (lane >> 2);
#pragma unroll
    for (int mi = 0; mi < 2; mi++) {
        const size_t cOff0 = (size_t)(coBase + mi * 16) * outHW;
        const size_t cOff8 = cOff0 + (size_t)8 * outHW;
#pragma unroll
        for (int nf = 0; nf < 8; nf++) {
            outP[cOff0 + off[nf*2  ]] = acc[mi][nf][0];
            outP[cOff0 + off[nf*2+1]] = acc[mi][nf][1];
            outP[cOff8 + off[nf*2  ]] = acc[mi][nf][2];
            outP[cOff8 + off[nf*2+1]] = acc[mi][nf][3];
        }
    }
}

// ---------------------------------------------------------------------------
// Per-channel batch stats -> (scale, shift). Deterministic tree reduction.
// ---------------------------------------------------------------------------
__global__ void stats_kernel(int bufSel, int bStride, int chanOff,
                             const float* __restrict__ gamma,
                             const float* __restrict__ beta,
                             int ssSel)
{
    const float* buf = pickBuf(bufSel);
    float* ss = pickSS(ssSel);
    const int c = blockIdx.x;
    const int tid = threadIdx.x;
    float s = 0.f, q = 0.f;
    for (int b = 0; b < BB; b++) {
        const float4* p = (const float4*)(buf + (size_t)(b * bStride + chanOff + c) * HWP);
        for (int i = tid; i < HWP / 4; i += 256) {
            float4 v = p[i];
            s += v.x + v.y + v.z + v.w;
            q += v.x * v.x + v.y * v.y + v.z * v.z + v.w * v.w;
        }
    }
    __shared__ float red[512];
    red[tid] = s; red[256 + tid] = q;
    __syncthreads();
    for (int off = 128; off > 0; off >>= 1) {
        if (tid < off) {
            red[tid]       += red[tid + off];
            red[256 + tid] += red[256 + tid + off];
        }
        __syncthreads();
    }
    if (tid == 0) {
        const float N = (float)(BB * HWP);
        float mean = red[0] / N;
        float var  = red[256] / N - mean * mean;
        float inv  = rsqrtf(var + 1e-5f);
        float scv  = gamma[c] * inv;
        ss[2 * c]     = scv;
        ss[2 * c + 1] = beta[c] - mean * scv;
    }
}

// out = relu(bn(y2) + bn(ysc))
__global__ void final_kernel(float* __restrict__ out)
{
    const int t  = blockIdx.x * 256 + threadIdx.x;
    const int p  = t % 4800;
    const int bc = t / 4800;
    const int b = bc >> 7, c = bc & 127;
    const float s2  = g_ss2[2 * c],  t2  = g_ss2[2 * c + 1];
    const float ssc = g_ssSC[2 * c], tsc = g_ssSC[2 * c + 1];
    const float4 a = ((const float4*)(g_y2   + (size_t)(b * 128 + c) * HWP))[p];
    const float4 d = ((const float4*)(g_ybig + (size_t)(b * 256 + 128 + c) * HWP))[p];
    float4 o;
    o.x = fmaxf(fmaf(a.x, s2, t2) + fmaf(d.x, ssc, tsc), 0.f);
    o.y = fmaxf(fmaf(a.y, s2, t2) + fmaf(d.y, ssc, tsc), 0.f);
    o.z = fmaxf(fmaf(a.z, s2, t2) + fmaf(d.z, ssc, tsc), 0.f);
    o.w = fmaxf(fmaf(a.w, s2, t2) + fmaf(d.w, ssc, tsc), 0.f);
    ((float4*)out)[t] = o;
}

// ---------------------------------------------------------------------------
extern "C" void kernel_launch(void* const* d_in, const int* in_sizes, int n_in,
                              void* d_out, int out_size)
{
    const float* x    = (const float*)d_in[0];
    const float* side = (const float*)d_in[1];
    const float* w1   = (const float*)d_in[2];
    const float* g1   = (const float*)d_in[3];
    const float* b1   = (const float*)d_in[4];
    const float* w11  = (const float*)d_in[5];
    const float* g11  = (const float*)d_in[6];
    const float* b11  = (const float*)d_in[7];
    const float* w2   = (const float*)d_in[8];
    const float* g2   = (const float*)d_in[9];
    const float* b2   = (const float*)d_in[10];
    const float* wsc  = (const float*)d_in[11];
    const float* gsc  = (const float*)d_in[12];
    const float* bsc  = (const float*)d_in[13];
    float* out = (float*)d_out;

    cudaFuncSetAttribute(conv_mma_kernel,
                         cudaFuncAttributeMaxDynamicSharedMemorySize, SMEM_BYTES);

    // 0) pre-split weights into bf16 hi/lo, [tap][co][ci]
    prep_kernel<<<(25*256*256 + 255)/256, 256>>>(w1, wsc, 256, 256, 25, 0);
    prep_kernel<<<( 9*128*256 + 255)/256, 256>>>(w11, nullptr, 128, 256, 9, 1);
    prep_kernel<<<( 9*128*128 + 255)/256, 256>>>(w2,  nullptr, 128, 128, 9, 2);

    // 0b) pre-split x into NHWC bf16 hi/lo
    {
        dim3 g(4800/64, 256/64, BB);
        actprep_kernel<<<g, 256>>>(-1, x, nullptr, CIN, 0, CIN, 256, 4800, 0, 0, 0);
    }

    // 1) sparse 5x5 conv (w1 -> ch 0..127, wsc -> ch 128..255 of g_ybig),
    //    4 parity launches over the 60x80 quad grid.
    dim3 gA(300, 2);
    const int cnt[5] = {9, 9, 6, 6, 4};
    const int pys[5] = {0, 0, 0, 1, 1};
    const int pxs[5] = {0, 0, 1, 0, 1};
    for (int set = 1; set <= 4; set++) {
        conv_mma_kernel<<<gA, 256, SMEM_BYTES>>>(
            /*actSel*/0, 256, 60, 80,
            /*wSel*/0, /*coT*/256, set, cnt[set],
            /*outSel*/0, 256,
            2, pys[set], 2, pxs[set], 160);
    }

    // 2) BN stats for both halves of g_ybig
    stats_kernel<<<128, 256>>>(0, 256, 0,   g1,  b1,  0);
    stats_kernel<<<128, 256>>>(0, 256, 128, gsc, bsc, 1);

    // 2b) build concat input: bn+relu(y1) ch 0..127, side ch 128..255 -> NHWC hi/lo
    {
        dim3 g(19200/64, 256/64, BB);
        actprep_kernel<<<g, 256>>>(0, nullptr, side, 256, 128, 128, 256, 19200, 1, 0, 1);
    }

    // 3) conv3x3 over concat -> y11
    dim3 g3(1200, 1);
    conv_mma_kernel<<<g3, 256, SMEM_BYTES>>>(
        /*actSel*/1, 256, 120, 160,
        /*wSel*/1, /*coT*/128, 0, 9,
        /*outSel*/1, 128,
        1, 0, 1, 0, 160);

    // 4) BN stats on y11; build a11 = relu(bn(y11)) NHWC hi/lo
    stats_kernel<<<128, 256>>>(1, 128, 0, g11, b11, 2);
    {
        dim3 g(19200/64, 128/64, BB);
        actprep_kernel<<<g, 256>>>(1, nullptr, nullptr, 128, 0, 128, 128, 19200, 1, 2, 2);
    }

    // 5) conv3x3 (Cin=128) -> y2
    conv_mma_kernel<<<g3, 256, SMEM_BYTES>>>(
        /*actSel*/2, 128, 120, 160,
        /*wSel*/2, /*coT*/128, 0, 9,
        /*outSel*/2, 128,
        1, 0, 1, 0, 160);

    // 6) BN stats for y2; final fuse: relu(bn(y2) + bn(ysc))
    stats_kernel<<<128, 256>>>(2, 128, 0, g2, b2, 3);
    final_kernel<<<19200, 256>>>(out);
}

// round 10
// speedup vs baseline: 2.2849x; 1.0385x over previous
#include <cuda_runtime.h>
#include <cuda_bf16.h>
#include <cstdint>
#include <cstddef>

#define BB   8
#define CIN  256
#define HWP  (120*160)   /* 19200 output plane size */

// ---------------- scratch (static device globals; no allocation) ----------------
__device__ float g_ybig[(size_t)BB * 256 * HWP]; // ch 0..127 conv1 raw, 128..255 shortcut raw
__device__ float g_y11 [(size_t)BB * 128 * HWP];
__device__ float g_y2  [(size_t)BB * 128 * HWP];
__device__ float g_ssA [256];   // (scale,shift) interleaved
__device__ float g_ssSC[256];
__device__ float g_ss11[256];
__device__ float g_ss2 [256];

// pre-split bf16 weights: [tap][co][ci], hi + lo
__device__ __nv_bfloat16 g_wA_hi [25 * 256 * 256];
__device__ __nv_bfloat16 g_wA_lo [25 * 256 * 256];
__device__ __nv_bfloat16 g_w11_hi[ 9 * 128 * 256];
__device__ __nv_bfloat16 g_w11_lo[ 9 * 128 * 256];
__device__ __nv_bfloat16 g_w2_hi [ 9 * 128 * 128];
__device__ __nv_bfloat16 g_w2_lo [ 9 * 128 * 128];

// pre-split bf16 activations, NHWC [b][pix][c], hi + lo
__device__ __nv_bfloat16 g_xa_hi [(size_t)BB *  4800 * 256];
__device__ __nv_bfloat16 g_xa_lo [(size_t)BB *  4800 * 256];
__device__ __nv_bfloat16 g_cat_hi[(size_t)BB * 19200 * 256];
__device__ __nv_bfloat16 g_cat_lo[(size_t)BB * 19200 * 256];
__device__ __nv_bfloat16 g_a11_hi[(size_t)BB * 19200 * 128];
__device__ __nv_bfloat16 g_a11_lo[(size_t)BB * 19200 * 128];

__device__ __forceinline__ float* pickBuf(int s) {
    return s == 0 ? g_ybig : (s == 1 ? g_y11 : g_y2);
}
__device__ __forceinline__ float* pickSS(int s) {
    return s == 0 ? g_ssA : (s == 1 ? g_ssSC : (s == 2 ? g_ss11 : g_ss2));
}
__device__ __forceinline__ __nv_bfloat16* pickWhi(int s) {
    return s == 0 ? g_wA_hi : (s == 1 ? g_w11_hi : g_w2_hi);
}
__device__ __forceinline__ __nv_bfloat16* pickWlo(int s) {
    return s == 0 ? g_wA_lo : (s == 1 ? g_w11_lo : g_w2_lo);
}
__device__ __forceinline__ __nv_bfloat16* pickAhi(int s) {
    return s == 0 ? g_xa_hi : (s == 1 ? g_cat_hi : g_a11_hi);
}
__device__ __forceinline__ __nv_bfloat16* pickAlo(int s) {
    return s == 0 ? g_xa_lo : (s == 1 ? g_cat_lo : g_a11_lo);
}

// ---------------- tap tables ----------------
// set0: 3x3 conv (9 taps). sets 1-4: parity decompositions of the sparse-upsample
// 5x5 conv; parity (py,px): set1=(0,0) 9, set2=(0,1) 6, set3=(1,0) 6, set4=(1,1) 4.
__constant__ int c_dy[5][9] = {
    {-1,-1,-1, 0,0,0, 1,1,1},
    {-1,-1,-1, 0,0,0, 1,1,1},
    {-1,-1, 0,0, 1,1, 0,0,0},
    { 0, 0, 0, 1,1,1, 0,0,0},
    { 0, 0, 1, 1, 0,0,0,0,0},
};
__constant__ int c_dx[5][9] = {
    {-1,0,1, -1,0,1, -1,0,1},
    {-1,0,1, -1,0,1, -1,0,1},
    { 0,1, 0,1, 0,1, 0,0,0},
    {-1,0,1, -1,0,1, 0,0,0},
    { 0,1, 0,1, 0,0,0,0,0},
};
__constant__ int c_wi[5][9] = {
    {0,1,2, 3,4,5, 6,7,8},
    {0,2,4, 10,12,14, 20,22,24},
    {1,3, 11,13, 21,23, 0,0,0},
    {5,7,9, 15,17,19, 0,0,0},
    {6,8, 16,18, 0,0,0,0,0},
};

// ---------------- PTX helpers (sm_80+ baseline — compiles at sm_100) ----------------
__device__ __forceinline__ uint32_t smem_u32(const void* p) {
    uint32_t a;
    asm("{ .reg .u64 t; cvta.to.shared.u64 t, %1; cvt.u32.u64 %0, t; }" : "=r"(a) : "l"(p));
    return a;
}
__device__ __forceinline__ void ldsm_x4(uint32_t* r, uint32_t addr) {
    asm volatile("ldmatrix.sync.aligned.m8n8.x4.shared.b16 {%0,%1,%2,%3}, [%4];"
                 : "=r"(r[0]), "=r"(r[1]), "=r"(r[2]), "=r"(r[3]) : "r"(addr));
}
__device__ __forceinline__ void mma_bf16(float* d, const uint32_t* a, const uint32_t* b) {
    asm volatile("mma.sync.aligned.m16n8k16.row.col.f32.bf16.bf16.f32 "
                 "{%0,%1,%2,%3},{%4,%5,%6,%7},{%8,%9},{%0,%1,%2,%3};"
                 : "+f"(d[0]), "+f"(d[1]), "+f"(d[2]), "+f"(d[3])
                 : "r"(a[0]), "r"(a[1]), "r"(a[2]), "r"(a[3]), "r"(b[0]), "r"(b[1]));
}
__device__ __forceinline__ void cp16(uint32_t dst, const void* src, uint32_t sz) {
    asm volatile("cp.async.cg.shared.global [%0], [%1], 16, %2;"
                 :: "r"(dst), "l"(src), "r"(sz) : "memory");
}
__device__ __forceinline__ void cp_commit() {
    asm volatile("cp.async.commit_group;" ::: "memory");
}
__device__ __forceinline__ void cp_wait1() {
    asm volatile("cp.async.wait_group 1;" ::: "memory");
}

// ---------------- SMEM layout: header + 2 pipeline stages ----------------
#define OFF_SB    0                    /* int[128] */
#define OFF_SY    512
#define OFF_SX    1024
#define OFF_STAGE 2048                 /* stage s at OFF_STAGE + s*65536 */
#define STG_A_HI  0                    /* 128co x 64ci bf16 = 16KB each */
#define STG_A_LO  16384
#define STG_B_HI  32768
#define STG_B_LO  49152
#define STAGE_BYTES 65536
#define SMEM_BYTES (OFF_STAGE + 2 * STAGE_BYTES)   /* 133120 */

// ---------------------------------------------------------------------------
// Weight pre-split: fp32 [co][ci][taps] (optionally two 128-co halves) ->
// bf16 hi/lo [tap][co][ci].
// ---------------------------------------------------------------------------
__global__ void prep_kernel(const float* __restrict__ s0, const float* __restrict__ s1,
                            int coT, int ciT, int taps, int sel)
{
    const int idx = blockIdx.x * 256 + threadIdx.x;
    const int total = taps * coT * ciT;
    if (idx >= total) return;
    const int ci = idx % ciT;
    const int co = (idx / ciT) % coT;
    const int tap = idx / (ciT * coT);
    const float* s = s0;
    int c = co;
    if (s1 != nullptr && co >= 128) { s = s1; c = co - 128; }
    const float v = s[((size_t)c * ciT + ci) * taps + tap];
    const __nv_bfloat16 h = __float2bfloat16(v);
    const __nv_bfloat16 l = __float2bfloat16(v - __bfloat162float(h));
    pickWhi(sel)[idx] = h;
    pickWlo(sel)[idx] = l;
}

// ---------------------------------------------------------------------------
// Activation pre-split: fp32 NCHW (virtual concat, optional fused BN+ReLU) ->
// bf16 hi/lo NHWC [b][pix][C]. Tile = 64 pixels x 64 channels with smem
// transpose so both reads and writes are coalesced.
// ---------------------------------------------------------------------------
__global__ __launch_bounds__(256)
void actprep_kernel(int inASel, const float* __restrict__ inAExt,
                    const float* __restrict__ inB,
                    int strA, int strB, int split, int C, int HW,
                    int useBn, int ssSel, int dstSel)
{
    __shared__ __nv_bfloat16 s_hi[64][72];
    __shared__ __nv_bfloat16 s_lo[64][72];
    const int tid = threadIdx.x;
    const int pix0 = blockIdx.x * 64;
    const int c0   = blockIdx.y * 64;
    const int b    = blockIdx.z;
    const float* inA = (inASel < 0) ? inAExt : pickBuf(inASel);
    const float* ss  = pickSS(ssSel);
    __nv_bfloat16* dhi = pickAhi(dstSel);
    __nv_bfloat16* dlo = pickAlo(dstSel);

    const int cSub = tid >> 6, pixL = tid & 63;
#pragma unroll 4
    for (int ci = 0; ci < 16; ci++) {
        const int cl = ci * 4 + cSub;
        const int c = c0 + cl;
        float v;
        if (c < split) {
            v = inA[((size_t)(b * strA + c)) * HW + pix0 + pixL];
            if (useBn) v = fmaxf(fmaf(v, ss[2 * c], ss[2 * c + 1]), 0.f);
        } else {
            v = inB[((size_t)(b * strB + (c - split))) * HW + pix0 + pixL];
        }
        const __nv_bfloat16 h = __float2bfloat16(v);
        s_hi[pixL][cl] = h;
        s_lo[pixL][cl] = __float2bfloat16(v - __bfloat162float(h));
    }
    __syncthreads();
    // write-out: 8 chunks (64 ch) x 32 pixels x 2 halves = full 64x64 tile
    const int chunk = tid & 7, pL0 = tid >> 3;
#pragma unroll
    for (int h = 0; h < 2; h++) {
        const int pL = pL0 + h * 32;
        const uint4 vh = *(const uint4*)&s_hi[pL][chunk * 8];
        const uint4 vl = *(const uint4*)&s_lo[pL][chunk * 8];
        const size_t doff = (size_t)(b * HW + pix0 + pL) * C + c0 + chunk * 8;
        *(uint4*)(dhi + doff) = vh;
        *(uint4*)(dlo + doff) = vl;
    }
}

// ---------------------------------------------------------------------------
// conv-as-tap-GEMM via mma.sync bf16 (hi/lo x 3 passes, fp32 acc).
// D[128 co][128 sp] per CTA, 8 warps 4(M)x2(N). 2-stage cp.async pipeline:
// iter i+1's A/B tiles prefetched while iter i's MMA runs.
// ---------------------------------------------------------------------------
__global__ __launch_bounds__(256, 1)
void conv_mma_kernel(
    int actSel, int C, int sH, int sW,
    int wSel, int coT,
    int tapSet, int tapCount,
    int outSel, int outBStride,
    int oyMul, int oyAdd, int oxMul, int oxAdd,
    int outW)
{
    extern __shared__ __align__(128) char smem[];
    const uint32_t sb = smem_u32(smem);
    int* s_bt = (int*)(smem + OFF_SB);
    int* s_yt = (int*)(smem + OFF_SY);
    int* s_xt = (int*)(smem + OFF_SX);

    const int tid = threadIdx.x;
    const int lane = tid & 31, wid = tid >> 5;
    const int wm = wid >> 1, wn = wid & 1;
    const int inHW = sH * sW;
    const int outHW = HWP;
    const int chanOff = blockIdx.y * 128;

    float* outP = pickBuf(outSel);

    if (tid < 128) {
        const int s = blockIdx.x * 128 + tid;
        const int b = s / inHW; const int r = s - b * inHW;
        const int y = r / sW;
        s_bt[tid] = b; s_yt[tid] = y; s_xt[tid] = r - y * sW;
    }
    __syncthreads();

    // staging thread mapping: (row 0..127) x (half 0..1)
    const int rowT  = tid & 127;
    const int halfT = tid >> 7;
    const __nv_bfloat16* actSrc = halfT ? pickAlo(actSel) : pickAhi(actSel);
    const __nv_bfloat16* wSrc   = halfT ? pickWlo(wSel)   : pickWhi(wSel);
    const uint32_t bDst0 = sb + OFF_STAGE + (halfT ? STG_B_LO : STG_B_HI) + rowT * 128;
    const uint32_t aDst0 = sb + OFF_STAGE + (halfT ? STG_A_LO : STG_A_HI) + rowT * 128;
    const int rSwz = rowT & 7;
    const int bT = s_bt[rowT], yT = s_yt[rowT], xT = s_xt[rowT];
    const size_t wRowBase = (size_t)(chanOff + rowT) * C;

    float acc[2][8][4];
#pragma unroll
    for (int i = 0; i < 2; i++)
#pragma unroll
        for (int j = 0; j < 8; j++)
#pragma unroll
            for (int k = 0; k < 4; k++) acc[i][j][k] = 0.f;

    // ldmatrix lane addressing (swizzled)
    const int sx = lane & 7;
    const uint32_t aRowBase = (uint32_t)(wm * 32 + (lane & 15)) * 128;
    const uint32_t bRowBase = (uint32_t)(wn * 64 + (lane & 7) + ((lane >> 4) << 3)) * 128;
    const int ka0 = lane >> 4;
    const int kb0 = (lane >> 3) & 1;

    const int nIter = (C >> 6) * tapCount;

    // ---- staging issue for iteration `it` into stage buffer `s` ----
    auto stage = [&](int it, int s) {
        const int cbi = it / tapCount;
        const int t   = it - cbi * tapCount;
        const int cb  = cbi << 6;
        const int dy = c_dy[tapSet][t], dx = c_dx[tapSet][t], wi = c_wi[tapSet][t];
        const uint32_t sOff = (uint32_t)s * STAGE_BYTES;
        // B: activation row (pixel rowT shifted by tap)
        {
            const int yy = yT + dy, xx = xT + dx;
            const bool inb = ((unsigned)yy < (unsigned)sH) && ((unsigned)xx < (unsigned)sW);
            const __nv_bfloat16* src = inb
                ? actSrc + (size_t)(bT * inHW + yy * sW + xx) * C + cb
                : actSrc;
            const uint32_t sz = inb ? 16u : 0u;
            const uint32_t d = bDst0 + sOff;
#pragma unroll
            for (int c8 = 0; c8 < 8; c8++)
                cp16(d + ((c8 ^ rSwz) << 4), src + c8 * 8, sz);
        }
        // A: weight row (co = rowT) for this tap
        {
            const __nv_bfloat16* src = wSrc + (size_t)wi * coT * C + wRowBase + cb;
            const uint32_t d = aDst0 + sOff;
#pragma unroll
            for (int c8 = 0; c8 < 8; c8++)
                cp16(d + ((c8 ^ rSwz) << 4), src + c8 * 8, 16u);
        }
    };

    // prologue: stage iter 0 into buffer 0
    stage(0, 0);
    cp_commit();

    for (int it = 0; it < nIter; it++) {
        // prefetch next iter into the other buffer (guarded by the barrier at
        // the end of the previous iteration: its MMA reads are complete).
        if (it + 1 < nIter) stage(it + 1, (it + 1) & 1);
        cp_commit();                   // possibly-empty group keeps count uniform
        cp_wait1();                    // all groups except newest -> iter `it` ready
        __syncthreads();

        const uint32_t stBase = sb + OFF_STAGE + (uint32_t)(it & 1) * STAGE_BYTES;
        // ---- 3 MMA passes: hi*hi, hi*lo, lo*hi ----
#pragma unroll
        for (int pass = 0; pass < 3; pass++) {
            const uint32_t Abase = stBase + ((pass == 2) ? STG_A_LO : STG_A_HI);
            const uint32_t Bbase = stBase + ((pass == 1) ? STG_B_LO : STG_B_HI);
#pragma unroll
            for (int k = 0; k < 4; k++) {
                const uint32_t aOff = (uint32_t)(((ka0 + 2 * k) ^ sx) << 4);
                const uint32_t bOff = (uint32_t)(((kb0 + 2 * k) ^ sx) << 4);
                uint32_t a0[4], a1[4];
                ldsm_x4(a0, Abase + aRowBase + aOff);
                ldsm_x4(a1, Abase + aRowBase + 16 * 128 + aOff);
#pragma unroll
                for (int tt = 0; tt < 4; tt++) {
                    uint32_t bb[4];
                    ldsm_x4(bb, Bbase + bRowBase + tt * 2048 + bOff);
                    mma_bf16(acc[0][tt*2  ], a0, bb);
                    mma_bf16(acc[0][tt*2+1], a0, bb + 2);
                    mma_bf16(acc[1][tt*2  ], a1, bb);
                    mma_bf16(acc[1][tt*2+1], a1, bb + 2);
                }
            }
        }
        __syncthreads();   // all warps done reading buf (it&1) before it is restaged
    }

    // ---- epilogue: registers -> global (fp32 NCHW scratch) ----
    uint32_t off[16];
#pragma unroll
    for (int i = 0; i < 16; i++) {
        const int nf = i >> 1, e = i & 1;
        const int spi = wn * 64 + nf * 8 + (lane & 3) * 2 + e;
        const int b = s_bt[spi];
        const int oy = s_yt[spi] * oyMul + oyAdd;
        const int ox = s_xt[spi] * oxMul + oxAdd;
        off[i] = (uint32_t)(b * outBStride) * (uint32_t)outHW
               + (uint32_t)(oy * outW + ox);
    }
    const int coBase = chanOff + wm * 32 + (lane >> 2);
#pragma unroll
    for (int mi = 0; mi < 2; mi++) {
        const size_t cOff0 = (size_t)(coBase + mi * 16) * outHW;
        const size_t cOff8 = cOff0 + (size_t)8 * outHW;
#pragma unroll
        for (int nf = 0; nf < 8; nf++) {
            outP[cOff0 + off[nf*2  ]] = acc[mi][nf][0];
            outP[cOff0 + off[nf*2+1]] = acc[mi][nf][1];
            outP[cOff8 + off[nf*2  ]] = acc[mi][nf][2];
            outP[cOff8 + off[nf*2+1]] = acc[mi][nf][3];
        }
    }
}

// ---------------------------------------------------------------------------
// Per-channel batch stats -> (scale, shift). Deterministic tree reduction.
// ---------------------------------------------------------------------------
__global__ void stats_kernel(int bufSel, int bStride, int chanOff,
                             const float* __restrict__ gamma,
                             const float* __restrict__ beta,
                             int ssSel)
{
    const float* buf = pickBuf(bufSel);
    float* ss = pickSS(ssSel);
    const int c = blockIdx.x;
    const int tid = threadIdx.x;
    float s = 0.f, q = 0.f;
    for (int b = 0; b < BB; b++) {
        const float4* p = (const float4*)(buf + (size_t)(b * bStride + chanOff + c) * HWP);
        for (int i = tid; i < HWP / 4; i += 256) {
            float4 v = p[i];
            s += v.x + v.y + v.z + v.w;
            q += v.x * v.x + v.y * v.y + v.z * v.z + v.w * v.w;
        }
    }
    __shared__ float red[512];
    red[tid] = s; red[256 + tid] = q;
    __syncthreads();
    for (int off = 128; off > 0; off >>= 1) {
        if (tid < off) {
            red[tid]       += red[tid + off];
            red[256 + tid] += red[256 + tid + off];
        }
        __syncthreads();
    }
    if (tid == 0) {
        const float N = (float)(BB * HWP);
        float mean = red[0] / N;
        float var  = red[256] / N - mean * mean;
        float inv  = rsqrtf(var + 1e-5f);
        float scv  = gamma[c] * inv;
        ss[2 * c]     = scv;
        ss[2 * c + 1] = beta[c] - mean * scv;
    }
}

// out = relu(bn(y2) + bn(ysc))
__global__ void final_kernel(float* __restrict__ out)
{
    const int t  = blockIdx.x * 256 + threadIdx.x;
    const int p  = t % 4800;
    const int bc = t / 4800;
    const int b = bc >> 7, c = bc & 127;
    const float s2  = g_ss2[2 * c],  t2  = g_ss2[2 * c + 1];
    const float ssc = g_ssSC[2 * c], tsc = g_ssSC[2 * c + 1];
    const float4 a = ((const float4*)(g_y2   + (size_t)(b * 128 + c) * HWP))[p];
    const float4 d = ((const float4*)(g_ybig + (size_t)(b * 256 + 128 + c) * HWP))[p];
    float4 o;
    o.x = fmaxf(fmaf(a.x, s2, t2) + fmaf(d.x, ssc, tsc), 0.f);
    o.y = fmaxf(fmaf(a.y, s2, t2) + fmaf(d.y, ssc, tsc), 0.f);
    o.z = fmaxf(fmaf(a.z, s2, t2) + fmaf(d.z, ssc, tsc), 0.f);
    o.w = fmaxf(fmaf(a.w, s2, t2) + fmaf(d.w, ssc, tsc), 0.f);
    ((float4*)out)[t] = o;
}

// ---------------------------------------------------------------------------
extern "C" void kernel_launch(void* const* d_in, const int* in_sizes, int n_in,
                              void* d_out, int out_size)
{
    const float* x    = (const float*)d_in[0];
    const float* side = (const float*)d_in[1];
    const float* w1   = (const float*)d_in[2];
    const float* g1   = (const float*)d_in[3];
    const float* b1   = (const float*)d_in[4];
    const float* w11  = (const float*)d_in[5];
    const float* g11  = (const float*)d_in[6];
    const float* b11  = (const float*)d_in[7];
    const float* w2   = (const float*)d_in[8];
    const float* g2   = (const float*)d_in[9];
    const float* b2   = (const float*)d_in[10];
    const float* wsc  = (const float*)d_in[11];
    const float* gsc  = (const float*)d_in[12];
    const float* bsc  = (const float*)d_in[13];
    float* out = (float*)d_out;

    cudaFuncSetAttribute(conv_mma_kernel,
                         cudaFuncAttributeMaxDynamicSharedMemorySize, SMEM_BYTES);

    // 0) pre-split weights into bf16 hi/lo, [tap][co][ci]
    prep_kernel<<<(25*256*256 + 255)/256, 256>>>(w1, wsc, 256, 256, 25, 0);
    prep_kernel<<<( 9*128*256 + 255)/256, 256>>>(w11, nullptr, 128, 256, 9, 1);
    prep_kernel<<<( 9*128*128 + 255)/256, 256>>>(w2,  nullptr, 128, 128, 9, 2);

    // 0b) pre-split x into NHWC bf16 hi/lo
    {
        dim3 g(4800/64, 256/64, BB);
        actprep_kernel<<<g, 256>>>(-1, x, nullptr, CIN, 0, CIN, 256, 4800, 0, 0, 0);
    }

    // 1) sparse 5x5 conv (w1 -> ch 0..127, wsc -> ch 128..255 of g_ybig),
    //    4 parity launches over the 60x80 quad grid.
    dim3 gA(300, 2);
    const int cnt[5] = {9, 9, 6, 6, 4};
    const int pys[5] = {0, 0, 0, 1, 1};
    const int pxs[5] = {0, 0, 1, 0, 1};
    for (int set = 1; set <= 4; set++) {
        conv_mma_kernel<<<gA, 256, SMEM_BYTES>>>(
            /*actSel*/0, 256, 60, 80,
            /*wSel*/0, /*coT*/256, set, cnt[set],
            /*outSel*/0, 256,
            2, pys[set], 2, pxs[set], 160);
    }

    // 2) BN stats for both halves of g_ybig
    stats_kernel<<<128, 256>>>(0, 256, 0,   g1,  b1,  0);
    stats_kernel<<<128, 256>>>(0, 256, 128, gsc, bsc, 1);

    // 2b) build concat input: bn+relu(y1) ch 0..127, side ch 128..255 -> NHWC hi/lo
    {
        dim3 g(19200/64, 256/64, BB);
        actprep_kernel<<<g, 256>>>(0, nullptr, side, 256, 128, 128, 256, 19200, 1, 0, 1);
    }

    // 3) conv3x3 over concat -> y11
    dim3 g3(1200, 1);
    conv_mma_kernel<<<g3, 256, SMEM_BYTES>>>(
        /*actSel*/1, 256, 120, 160,
        /*wSel*/1, /*coT*/128, 0, 9,
        /*outSel*/1, 128,
        1, 0, 1, 0, 160);

    // 4) BN stats on y11; build a11 = relu(bn(y11)) NHWC hi/lo
    stats_kernel<<<128, 256>>>(1, 128, 0, g11, b11, 2);
    {
        dim3 g(19200/64, 128/64, BB);
        actprep_kernel<<<g, 256>>>(1, nullptr, nullptr, 128, 0, 128, 128, 19200, 1, 2, 2);
    }

    // 5) conv3x3 (Cin=128) -> y2
    conv_mma_kernel<<<g3, 256, SMEM_BYTES>>>(
        /*actSel*/2, 128, 120, 160,
        /*wSel*/2, /*coT*/128, 0, 9,
        /*outSel*/2, 128,
        1, 0, 1, 0, 160);

    // 6) BN stats for y2; final fuse: relu(bn(y2) + bn(ysc))
    stats_kernel<<<128, 256>>>(2, 128, 0, g2, b2, 3);
    final_kernel<<<19200, 256>>>(out);
}

// round 11
// speedup vs baseline: 3.5001x; 1.5319x over previous
#include <cuda_runtime.h>
#include <cuda_fp16.h>
#include <cstdint>
#include <cstddef>

#define BB   8
#define CIN  256
#define HWP  (120*160)   /* 19200 output plane size */

// ---------------- scratch (static device globals; no allocation) ----------------
__device__ float g_ybig[(size_t)BB * 256 * HWP]; // ch 0..127 conv1 raw, 128..255 shortcut raw
__device__ float g_y11 [(size_t)BB * 128 * HWP];
__device__ float g_y2  [(size_t)BB * 128 * HWP];
__device__ float g_ssA [256];   // (scale,shift) interleaved
__device__ float g_ssSC[256];
__device__ float g_ss11[256];
__device__ float g_ss2 [256];

// pre-split fp16 weights: [tap][co][ci], hi + lo (A operand, ~21-bit effective)
__device__ __half g_wA_hi [25 * 256 * 256];
__device__ __half g_wA_lo [25 * 256 * 256];
__device__ __half g_w11_hi[ 9 * 128 * 256];
__device__ __half g_w11_lo[ 9 * 128 * 256];
__device__ __half g_w2_hi [ 9 * 128 * 128];
__device__ __half g_w2_lo [ 9 * 128 * 128];

// fp16 activations, NHWC [b][pix][c] (B operand, single precision level)
__device__ __half g_xa [(size_t)BB *  4800 * 256];
__device__ __half g_cat[(size_t)BB * 19200 * 256];
__device__ __half g_a11[(size_t)BB * 19200 * 128];

__device__ __forceinline__ float* pickBuf(int s) {
    return s == 0 ? g_ybig : (s == 1 ? g_y11 : g_y2);
}
__device__ __forceinline__ float* pickSS(int s) {
    return s == 0 ? g_ssA : (s == 1 ? g_ssSC : (s == 2 ? g_ss11 : g_ss2));
}
__device__ __forceinline__ __half* pickWhi(int s) {
    return s == 0 ? g_wA_hi : (s == 1 ? g_w11_hi : g_w2_hi);
}
__device__ __forceinline__ __half* pickWlo(int s) {
    return s == 0 ? g_wA_lo : (s == 1 ? g_w11_lo : g_w2_lo);
}
__device__ __forceinline__ __half* pickAct(int s) {
    return s == 0 ? g_xa : (s == 1 ? g_cat : g_a11);
}

// ---------------- tap tables ----------------
// set0: 3x3 conv (9 taps). sets 1-4: parity decompositions of the sparse-upsample
// 5x5 conv; parity (py,px): set1=(0,0) 9, set2=(0,1) 6, set3=(1,0) 6, set4=(1,1) 4.
__constant__ int c_dy[5][9] = {
    {-1,-1,-1, 0,0,0, 1,1,1},
    {-1,-1,-1, 0,0,0, 1,1,1},
    {-1,-1, 0,0, 1,1, 0,0,0},
    { 0, 0, 0, 1,1,1, 0,0,0},
    { 0, 0, 1, 1, 0,0,0,0,0},
};
__constant__ int c_dx[5][9] = {
    {-1,0,1, -1,0,1, -1,0,1},
    {-1,0,1, -1,0,1, -1,0,1},
    { 0,1, 0,1, 0,1, 0,0,0},
    {-1,0,1, -1,0,1, 0,0,0},
    { 0,1, 0,1, 0,0,0,0,0},
};
__constant__ int c_wi[5][9] = {
    {0,1,2, 3,4,5, 6,7,8},
    {0,2,4, 10,12,14, 20,22,24},
    {1,3, 11,13, 21,23, 0,0,0},
    {5,7,9, 15,17,19, 0,0,0},
    {6,8, 16,18, 0,0,0,0,0},
};

// ---------------- PTX helpers (sm_80+ baseline — compiles at sm_100) ----------------
__device__ __forceinline__ uint32_t smem_u32(const void* p) {
    uint32_t a;
    asm("{ .reg .u64 t; cvta.to.shared.u64 t, %1; cvt.u32.u64 %0, t; }" : "=r"(a) : "l"(p));
    return a;
}
__device__ __forceinline__ void ldsm_x4(uint32_t* r, uint32_t addr) {
    asm volatile("ldmatrix.sync.aligned.m8n8.x4.shared.b16 {%0,%1,%2,%3}, [%4];"
                 : "=r"(r[0]), "=r"(r[1]), "=r"(r[2]), "=r"(r[3]) : "r"(addr));
}
__device__ __forceinline__ void mma_f16(float* d, const uint32_t* a, const uint32_t* b) {
    asm volatile("mma.sync.aligned.m16n8k16.row.col.f32.f16.f16.f32 "
                 "{%0,%1,%2,%3},{%4,%5,%6,%7},{%8,%9},{%0,%1,%2,%3};"
                 : "+f"(d[0]), "+f"(d[1]), "+f"(d[2]), "+f"(d[3])
                 : "r"(a[0]), "r"(a[1]), "r"(a[2]), "r"(a[3]), "r"(b[0]), "r"(b[1]));
}
__device__ __forceinline__ void cp16(uint32_t dst, const void* src, uint32_t sz) {
    asm volatile("cp.async.cg.shared.global [%0], [%1], 16, %2;"
                 :: "r"(dst), "l"(src), "r"(sz) : "memory");
}
__device__ __forceinline__ void cp_commit() {
    asm volatile("cp.async.commit_group;" ::: "memory");
}
__device__ __forceinline__ void cp_wait1() {
    asm volatile("cp.async.wait_group 1;" ::: "memory");
}

// ---------------- SMEM layout: header + 3 pipeline stages ----------------
#define OFF_SB    0                    /* int[128] */
#define OFF_SY    512
#define OFF_SX    1024
#define OFF_STAGE 2048
#define STG_A_HI  0                    /* 128co x 64ci fp16 = 16KB */
#define STG_A_LO  16384
#define STG_B     32768                /* 128sp x 64ci fp16 = 16KB */
#define STAGE_BYTES 49152
#define NSTAGE    3
#define SMEM_BYTES (OFF_STAGE + NSTAGE * STAGE_BYTES)   /* 149504 */

// ---------------------------------------------------------------------------
// Weight pre-split: fp32 [co][ci][taps] (optionally two 128-co halves) ->
// fp16 hi/lo [tap][co][ci].
// ---------------------------------------------------------------------------
__global__ void prep_kernel(const float* __restrict__ s0, const float* __restrict__ s1,
                            int coT, int ciT, int taps, int sel)
{
    const int idx = blockIdx.x * 256 + threadIdx.x;
    const int total = taps * coT * ciT;
    if (idx >= total) return;
    const int ci = idx % ciT;
    const int co = (idx / ciT) % coT;
    const int tap = idx / (ciT * coT);
    const float* s = s0;
    int c = co;
    if (s1 != nullptr && co >= 128) { s = s1; c = co - 128; }
    const float v = s[((size_t)c * ciT + ci) * taps + tap];
    const __half h = __float2half_rn(v);
    const __half l = __float2half_rn(v - __half2float(h));
    pickWhi(sel)[idx] = h;
    pickWlo(sel)[idx] = l;
}

// ---------------------------------------------------------------------------
// Activation prep: fp32 NCHW (virtual concat, optional fused BN+ReLU) ->
// fp16 NHWC [b][pix][C]. Tile = 64 pixels x 64 channels with smem transpose.
// ---------------------------------------------------------------------------
__global__ __launch_bounds__(256)
void actprep_kernel(int inASel, const float* __restrict__ inAExt,
                    const float* __restrict__ inB,
                    int strA, int strB, int split, int C, int HW,
                    int useBn, int ssSel, int dstSel)
{
    __shared__ __half s_t[64][72];
    const int tid = threadIdx.x;
    const int pix0 = blockIdx.x * 64;
    const int c0   = blockIdx.y * 64;
    const int b    = blockIdx.z;
    const float* inA = (inASel < 0) ? inAExt : pickBuf(inASel);
    const float* ss  = pickSS(ssSel);
    __half* dst = pickAct(dstSel);

    const int cSub = tid >> 6, pixL = tid & 63;
#pragma unroll 4
    for (int ci = 0; ci < 16; ci++) {
        const int cl = ci * 4 + cSub;
        const int c = c0 + cl;
        float v;
        if (c < split) {
            v = inA[((size_t)(b * strA + c)) * HW + pix0 + pixL];
            if (useBn) v = fmaxf(fmaf(v, ss[2 * c], ss[2 * c + 1]), 0.f);
        } else {
            v = inB[((size_t)(b * strB + (c - split))) * HW + pix0 + pixL];
        }
        s_t[pixL][cl] = __float2half_rn(v);
    }
    __syncthreads();
    // write-out: 8 chunks (64 ch) x 32 pixels x 2 halves = full 64x64 tile
    const int chunk = tid & 7, pL0 = tid >> 3;
#pragma unroll
    for (int h = 0; h < 2; h++) {
        const int pL = pL0 + h * 32;
        const uint4 vh = *(const uint4*)&s_t[pL][chunk * 8];
        const size_t doff = (size_t)(b * HW + pix0 + pL) * C + c0 + chunk * 8;
        *(uint4*)(dst + doff) = vh;
    }
}

// ---------------------------------------------------------------------------
// conv-as-tap-GEMM via mma.sync fp16 (A = weight hi/lo 2 passes, B = fp16 act,
// fp32 accum). D[128 co][128 sp] per CTA, 8 warps 4(M)x2(N). 3-stage cp.async
// pipeline (depth-2 prefetch), single barrier per iteration.
// ---------------------------------------------------------------------------
__global__ __launch_bounds__(256, 1)
void conv_mma_kernel(
    int actSel, int C, int sH, int sW,
    int wSel, int coT,
    int tapSet, int tapCount,
    int outSel, int outBStride,
    int oyMul, int oyAdd, int oxMul, int oxAdd,
    int outW)
{
    extern __shared__ __align__(128) char smem[];
    const uint32_t sb = smem_u32(smem);
    int* s_bt = (int*)(smem + OFF_SB);
    int* s_yt = (int*)(smem + OFF_SY);
    int* s_xt = (int*)(smem + OFF_SX);

    const int tid = threadIdx.x;
    const int lane = tid & 31, wid = tid >> 5;
    const int wm = wid >> 1, wn = wid & 1;
    const int inHW = sH * sW;
    const int outHW = HWP;
    const int chanOff = blockIdx.y * 128;

    float* outP = pickBuf(outSel);
    const __half* act = pickAct(actSel);

    if (tid < 128) {
        const int s = blockIdx.x * 128 + tid;
        const int b = s / inHW; const int r = s - b * inHW;
        const int y = r / sW;
        s_bt[tid] = b; s_yt[tid] = y; s_xt[tid] = r - y * sW;
    }
    __syncthreads();

    // ---- staging thread mapping ----
    // B: 2 threads per spatial row (4 x 16B chunks each)
    const int rowB = tid >> 1, partB = tid & 1;
    const int bB = s_bt[rowB], yB = s_yt[rowB], xB = s_xt[rowB];
    const uint32_t bDst0 = sb + OFF_STAGE + STG_B + rowB * 128;
    const int swzB = rowB & 7;
    // A: 1 thread per (co row, hi/lo half), 8 x 16B chunks each
    const int rowA = tid & 127, halfA = tid >> 7;
    const __half* wSrc = halfA ? pickWlo(wSel) : pickWhi(wSel);
    const uint32_t aDst0 = sb + OFF_STAGE + (halfA ? STG_A_LO : STG_A_HI) + rowA * 128;
    const int swzA = rowA & 7;
    const size_t wRowBase = (size_t)(chanOff + rowA) * C;

    float acc[2][8][4];
#pragma unroll
    for (int i = 0; i < 2; i++)
#pragma unroll
        for (int j = 0; j < 8; j++)
#pragma unroll
            for (int k = 0; k < 4; k++) acc[i][j][k] = 0.f;

    // ldmatrix lane addressing (XOR swizzle on 128B rows)
    const int sx = lane & 7;
    const uint32_t aRowBase = (uint32_t)(wm * 32 + (lane & 15)) * 128;
    const uint32_t bRowBase = (uint32_t)(wn * 64 + (lane & 7) + ((lane >> 4) << 3)) * 128;
    const int ka0 = lane >> 4;
    const int kb0 = (lane >> 3) & 1;

    const int nIter = (C >> 6) * tapCount;

    // ---- staging issue for iteration `it` into stage buffer `s` (0..2) ----
    auto stage = [&](int it, int s) {
        const int cbi = it / tapCount;
        const int t   = it - cbi * tapCount;
        const int cb  = cbi << 6;
        const int dy = c_dy[tapSet][t], dx = c_dx[tapSet][t], wi = c_wi[tapSet][t];
        const uint32_t sOff = (uint32_t)s * STAGE_BYTES;
        // B: fp16 activation row for pixel rowB shifted by tap
        {
            const int yy = yB + dy, xx = xB + dx;
            const bool inb = ((unsigned)yy < (unsigned)sH) && ((unsigned)xx < (unsigned)sW);
            const __half* src = inb
                ? act + (size_t)(bB * inHW + yy * sW + xx) * C + cb
                : act;
            const uint32_t sz = inb ? 16u : 0u;
            const uint32_t d = bDst0 + sOff;
#pragma unroll
            for (int j = 0; j < 4; j++) {
                const int c8 = partB * 4 + j;
                cp16(d + ((c8 ^ swzB) << 4), src + c8 * 8, sz);
            }
        }
        // A: weight row (co = rowA, half = halfA) for this tap
        {
            const __half* src = wSrc + (size_t)wi * coT * C + wRowBase + cb;
            const uint32_t d = aDst0 + sOff;
#pragma unroll
            for (int c8 = 0; c8 < 8; c8++)
                cp16(d + ((c8 ^ swzA) << 4), src + c8 * 8, 16u);
        }
    };

    // prologue: stage iters 0 and 1 (nIter >= 16 always)
    stage(0, 0); cp_commit();
    stage(1, 1); cp_commit();

    int st = 0;          // it % 3
    int st2 = 2;         // (it+2) % 3
    for (int it = 0; it < nIter; it++) {
        cp_wait1();          // group `it` complete (group it+1 still in flight)
        __syncthreads();     // data visible to all; all warps done with MMA(it-1)

        // depth-2 prefetch into buffer (it+2)%3 (last read by MMA(it-1))
        if (it + 2 < nIter) stage(it + 2, st2);
        cp_commit();         // possibly-empty group keeps the count uniform

        const uint32_t stBase = sb + OFF_STAGE + (uint32_t)st * STAGE_BYTES;
        const uint32_t AbaseH = stBase + STG_A_HI;
        const uint32_t AbaseL = stBase + STG_A_LO;
        const uint32_t Bbase  = stBase + STG_B;
#pragma unroll
        for (int k = 0; k < 4; k++) {
            const uint32_t aOff = (uint32_t)(((ka0 + 2 * k) ^ sx) << 4);
            const uint32_t bOff = (uint32_t)(((kb0 + 2 * k) ^ sx) << 4);
            uint32_t bb[4][4];
#pragma unroll
            for (int tt = 0; tt < 4; tt++)
                ldsm_x4(bb[tt], Bbase + bRowBase + tt * 2048 + bOff);
            // pass 1: A_hi
            {
                uint32_t a0[4], a1[4];
                ldsm_x4(a0, AbaseH + aRowBase + aOff);
                ldsm_x4(a1, AbaseH + aRowBase + 16 * 128 + aOff);
#pragma unroll
                for (int tt = 0; tt < 4; tt++) {
                    mma_f16(acc[0][tt*2  ], a0, bb[tt]);
                    mma_f16(acc[0][tt*2+1], a0, bb[tt] + 2);
                    mma_f16(acc[1][tt*2  ], a1, bb[tt]);
                    mma_f16(acc[1][tt*2+1], a1, bb[tt] + 2);
                }
            }
            // pass 2: A_lo (same B fragments)
            {
                uint32_t a0[4], a1[4];
                ldsm_x4(a0, AbaseL + aRowBase + aOff);
                ldsm_x4(a1, AbaseL + aRowBase + 16 * 128 + aOff);
#pragma unroll
                for (int tt = 0; tt < 4; tt++) {
                    mma_f16(acc[0][tt*2  ], a0, bb[tt]);
                    mma_f16(acc[0][tt*2+1], a0, bb[tt] + 2);
                    mma_f16(acc[1][tt*2  ], a1, bb[tt]);
                    mma_f16(acc[1][tt*2+1], a1, bb[tt] + 2);
                }
            }
        }
        st  = (st  == 2) ? 0 : st  + 1;
        st2 = (st2 == 2) ? 0 : st2 + 1;
    }

    // ---- epilogue: registers -> global (fp32 NCHW scratch) ----
    uint32_t off[16];
#pragma unroll
    for (int i = 0; i < 16; i++) {
        const int nf = i >> 1, e = i & 1;
        const int spi = wn * 64 + nf * 8 + (lane & 3) * 2 + e;
        const int b = s_bt[spi];
        const int oy = s_yt[spi] * oyMul + oyAdd;
        const int ox = s_xt[spi] * oxMul + oxAdd;
        off[i] = (uint32_t)(b * outBStride) * (uint32_t)outHW
               + (uint32_t)(oy * outW + ox);
    }
    const int coBase = chanOff + wm * 32 + (lane >> 2);
#pragma unroll
    for (int mi = 0; mi < 2; mi++) {
        const size_t cOff0 = (size_t)(coBase + mi * 16) * outHW;
        const size_t cOff8 = cOff0 + (size_t)8 * outHW;
#pragma unroll
        for (int nf = 0; nf < 8; nf++) {
            outP[cOff0 + off[nf*2  ]] = acc[mi][nf][0];
            outP[cOff0 + off[nf*2+1]] = acc[mi][nf][1];
            outP[cOff8 + off[nf*2  ]] = acc[mi][nf][2];
            outP[cOff8 + off[nf*2+1]] = acc[mi][nf][3];
        }
    }
}

// ---------------------------------------------------------------------------
// Per-channel batch stats -> (scale, shift). Deterministic tree reduction.
// ---------------------------------------------------------------------------
__global__ void stats_kernel(int bufSel, int bStride, int chanOff,
                             const float* __restrict__ gamma,
                             const float* __restrict__ beta,
                             int ssSel)
{
    const float* buf = pickBuf(bufSel);
    float* ss = pickSS(ssSel);
    const int c = blockIdx.x;
    const int tid = threadIdx.x;
    float s = 0.f, q = 0.f;
    for (int b = 0; b < BB; b++) {
        const float4* p = (const float4*)(buf + (size_t)(b * bStride + chanOff + c) * HWP);
        for (int i = tid; i < HWP / 4; i += 256) {
            float4 v = p[i];
            s += v.x + v.y + v.z + v.w;
            q += v.x * v.x + v.y * v.y + v.z * v.z + v.w * v.w;
        }
    }
    __shared__ float red[512];
    red[tid] = s; red[256 + tid] = q;
    __syncthreads();
    for (int off = 128; off > 0; off >>= 1) {
        if (tid < off) {
            red[tid]       += red[tid + off];
            red[256 + tid] += red[256 + tid + off];
        }
        __syncthreads();
    }
    if (tid == 0) {
        const float N = (float)(BB * HWP);
        float mean = red[0] / N;
        float var  = red[256] / N - mean * mean;
        float inv  = rsqrtf(var + 1e-5f);
        float scv  = gamma[c] * inv;
        ss[2 * c]     = scv;
        ss[2 * c + 1] = beta[c] - mean * scv;
    }
}

// out = relu(bn(y2) + bn(ysc))
__global__ void final_kernel(float* __restrict__ out)
{
    const int t  = blockIdx.x * 256 + threadIdx.x;
    const int p  = t % 4800;
    const int bc = t / 4800;
    const int b = bc >> 7, c = bc & 127;
    const float s2  = g_ss2[2 * c],  t2  = g_ss2[2 * c + 1];
    const float ssc = g_ssSC[2 * c], tsc = g_ssSC[2 * c + 1];
    const float4 a = ((const float4*)(g_y2   + (size_t)(b * 128 + c) * HWP))[p];
    const float4 d = ((const float4*)(g_ybig + (size_t)(b * 256 + 128 + c) * HWP))[p];
    float4 o;
    o.x = fmaxf(fmaf(a.x, s2, t2) + fmaf(d.x, ssc, tsc), 0.f);
    o.y = fmaxf(fmaf(a.y, s2, t2) + fmaf(d.y, ssc, tsc), 0.f);
    o.z = fmaxf(fmaf(a.z, s2, t2) + fmaf(d.z, ssc, tsc), 0.f);
    o.w = fmaxf(fmaf(a.w, s2, t2) + fmaf(d.w, ssc, tsc), 0.f);
    ((float4*)out)[t] = o;
}

// ---------------------------------------------------------------------------
extern "C" void kernel_launch(void* const* d_in, const int* in_sizes, int n_in,
                              void* d_out, int out_size)
{
    const float* x    = (const float*)d_in[0];
    const float* side = (const float*)d_in[1];
    const float* w1   = (const float*)d_in[2];
    const float* g1   = (const float*)d_in[3];
    const float* b1   = (const float*)d_in[4];
    const float* w11  = (const float*)d_in[5];
    const float* g11  = (const float*)d_in[6];
    const float* b11  = (const float*)d_in[7];
    const float* w2   = (const float*)d_in[8];
    const float* g2   = (const float*)d_in[9];
    const float* b2   = (const float*)d_in[10];
    const float* wsc  = (const float*)d_in[11];
    const float* gsc  = (const float*)d_in[12];
    const float* bsc  = (const float*)d_in[13];
    float* out = (float*)d_out;

    cudaFuncSetAttribute(conv_mma_kernel,
                         cudaFuncAttributeMaxDynamicSharedMemorySize, SMEM_BYTES);

    // 0) pre-split weights into fp16 hi/lo, [tap][co][ci]
    prep_kernel<<<(25*256*256 + 255)/256, 256>>>(w1, wsc, 256, 256, 25, 0);
    prep_kernel<<<( 9*128*256 + 255)/256, 256>>>(w11, nullptr, 128, 256, 9, 1);
    prep_kernel<<<( 9*128*128 + 255)/256, 256>>>(w2,  nullptr, 128, 128, 9, 2);

    // 0b) x -> fp16 NHWC
    {
        dim3 g(4800/64, 256/64, BB);
        actprep_kernel<<<g, 256>>>(-1, x, nullptr, CIN, 0, CIN, 256, 4800, 0, 0, 0);
    }

    // 1) sparse 5x5 conv (w1 -> ch 0..127, wsc -> ch 128..255 of g_ybig),
    //    4 parity launches over the 60x80 quad grid.
    dim3 gA(300, 2);
    const int cnt[5] = {9, 9, 6, 6, 4};
    const int pys[5] = {0, 0, 0, 1, 1};
    const int pxs[5] = {0, 0, 1, 0, 1};
    for (int set = 1; set <= 4; set++) {
        conv_mma_kernel<<<gA, 256, SMEM_BYTES>>>(
            /*actSel*/0, 256, 60, 80,
            /*wSel*/0, /*coT*/256, set, cnt[set],
            /*outSel*/0, 256,
            2, pys[set], 2, pxs[set], 160);
    }

    // 2) BN stats for both halves of g_ybig
    stats_kernel<<<128, 256>>>(0, 256, 0,   g1,  b1,  0);
    stats_kernel<<<128, 256>>>(0, 256, 128, gsc, bsc, 1);

    // 2b) concat input: bn+relu(y1) ch 0..127, side ch 128..255 -> fp16 NHWC
    {
        dim3 g(19200/64, 256/64, BB);
        actprep_kernel<<<g, 256>>>(0, nullptr, side, 256, 128, 128, 256, 19200, 1, 0, 1);
    }

    // 3) conv3x3 over concat -> y11
    dim3 g3(1200, 1);
    conv_mma_kernel<<<g3, 256, SMEM_BYTES>>>(
        /*actSel*/1, 256, 120, 160,
        /*wSel*/1, /*coT*/128, 0, 9,
        /*outSel*/1, 128,
        1, 0, 1, 0, 160);

    // 4) BN stats on y11; a11 = relu(bn(y11)) -> fp16 NHWC
    stats_kernel<<<128, 256>>>(1, 128, 0, g11, b11, 2);
    {
        dim3 g(19200/64, 128/64, BB);
        actprep_kernel<<<g, 256>>>(1, nullptr, nullptr, 128, 0, 128, 128, 19200, 1, 2, 2);
    }

    // 5) conv3x3 (Cin=128) -> y2
    conv_mma_kernel<<<g3, 256, SMEM_BYTES>>>(
        /*actSel*/2, 128, 120, 160,
        /*wSel*/2, /*coT*/128, 0, 9,
        /*outSel*/2, 128,
        1, 0, 1, 0, 160);

    // 6) BN stats for y2; final fuse: relu(bn(y2) + bn(ysc))
    stats_kernel<<<128, 256>>>(2, 128, 0, g2, b2, 3);
    final_kernel<<<19200, 256>>>(out);
}

// round 12
// speedup vs baseline: 6.9226x; 1.9778x over previous
#include <cuda_runtime.h>
#include <cuda_fp16.h>
#include <cstdint>
#include <cstddef>

#define BB   8
#define CIN  256
#define HWP  (120*160)   /* 19200 output plane size */

// ---------------- scratch (static device globals; no allocation) ----------------
__device__ float g_ybig[(size_t)BB * 256 * HWP]; // ch 0..127 conv1 raw, 128..255 shortcut raw
__device__ float g_y11 [(size_t)BB * 128 * HWP];
__device__ float g_y2  [(size_t)BB * 128 * HWP];
__device__ float g_ssA [256];   // (scale,shift) interleaved
__device__ float g_ssSC[256];
__device__ float g_ss11[256];
__device__ float g_ss2 [256];

// fp16 weights: [tap][co][ci]
__device__ __half g_wA [25 * 256 * 256];
__device__ __half g_w11[ 9 * 128 * 256];
__device__ __half g_w2 [ 9 * 128 * 128];

// fp16 activations, NHWC [b][pix][c]
__device__ __half g_xa [(size_t)BB *  4800 * 256];
__device__ __half g_cat[(size_t)BB * 19200 * 256];
__device__ __half g_a11[(size_t)BB * 19200 * 128];

__device__ __forceinline__ float* pickBuf(int s) {
    return s == 0 ? g_ybig : (s == 1 ? g_y11 : g_y2);
}
__device__ __forceinline__ float* pickSS(int s) {
    return s == 0 ? g_ssA : (s == 1 ? g_ssSC : (s == 2 ? g_ss11 : g_ss2));
}
__device__ __forceinline__ __half* pickW(int s) {
    return s == 0 ? g_wA : (s == 1 ? g_w11 : g_w2);
}
__device__ __forceinline__ __half* pickAct(int s) {
    return s == 0 ? g_xa : (s == 1 ? g_cat : g_a11);
}

// ---------------- tap tables ----------------
// set0: 3x3 conv (9 taps). sets 1-4: parity decompositions of the sparse-upsample
// 5x5 conv; parity (py,px): set1=(0,0) 9, set2=(0,1) 6, set3=(1,0) 6, set4=(1,1) 4.
__constant__ int c_dy[5][9] = {
    {-1,-1,-1, 0,0,0, 1,1,1},
    {-1,-1,-1, 0,0,0, 1,1,1},
    {-1,-1, 0,0, 1,1, 0,0,0},
    { 0, 0, 0, 1,1,1, 0,0,0},
    { 0, 0, 1, 1, 0,0,0,0,0},
};
__constant__ int c_dx[5][9] = {
    {-1,0,1, -1,0,1, -1,0,1},
    {-1,0,1, -1,0,1, -1,0,1},
    { 0,1, 0,1, 0,1, 0,0,0},
    {-1,0,1, -1,0,1, 0,0,0},
    { 0,1, 0,1, 0,0,0,0,0},
};
__constant__ int c_wi[5][9] = {
    {0,1,2, 3,4,5, 6,7,8},
    {0,2,4, 10,12,14, 20,22,24},
    {1,3, 11,13, 21,23, 0,0,0},
    {5,7,9, 15,17,19, 0,0,0},
    {6,8, 16,18, 0,0,0,0,0},
};

// ---------------- PTX helpers (sm_80+ baseline — compiles at sm_100) ----------------
__device__ __forceinline__ uint32_t smem_u32(const void* p) {
    uint32_t a;
    asm("{ .reg .u64 t; cvta.to.shared.u64 t, %1; cvt.u32.u64 %0, t; }" : "=r"(a) : "l"(p));
    return a;
}
__device__ __forceinline__ void ldsm_x4(uint32_t* r, uint32_t addr) {
    asm volatile("ldmatrix.sync.aligned.m8n8.x4.shared.b16 {%0,%1,%2,%3}, [%4];"
                 : "=r"(r[0]), "=r"(r[1]), "=r"(r[2]), "=r"(r[3]) : "r"(addr));
}
__device__ __forceinline__ void mma_f16(float* d, const uint32_t* a, const uint32_t* b) {
    asm volatile("mma.sync.aligned.m16n8k16.row.col.f32.f16.f16.f32 "
                 "{%0,%1,%2,%3},{%4,%5,%6,%7},{%8,%9},{%0,%1,%2,%3};"
                 : "+f"(d[0]), "+f"(d[1]), "+f"(d[2]), "+f"(d[3])
                 : "r"(a[0]), "r"(a[1]), "r"(a[2]), "r"(a[3]), "r"(b[0]), "r"(b[1]));
}
__device__ __forceinline__ void cp16(uint32_t dst, const void* src, uint32_t sz) {
    asm volatile("cp.async.cg.shared.global [%0], [%1], 16, %2;"
                 :: "r"(dst), "l"(src), "r"(sz) : "memory");
}
__device__ __forceinline__ void cp_commit() {
    asm volatile("cp.async.commit_group;" ::: "memory");
}
__device__ __forceinline__ void cp_wait1() {
    asm volatile("cp.async.wait_group 1;" ::: "memory");
}

// ---------------- SMEM layout: header + 3 pipeline stages (32KB each) ----------------
#define OFF_SB    0                    /* int[128] */
#define OFF_SY    512
#define OFF_SX    1024
#define OFF_STAGE 2048
#define STG_A     0                    /* 128co x 64ci fp16 = 16KB */
#define STG_B     16384                /* 128sp x 64ci fp16 = 16KB */
#define STAGE_BYTES 32768
#define NSTAGE    3
#define SMEM_BYTES (OFF_STAGE + NSTAGE * STAGE_BYTES)   /* 100352 -> 2 CTAs/SM */

// ---------------------------------------------------------------------------
// Weight prep: fp32 [co][ci][taps] (optionally two 128-co halves) ->
// fp16 [tap][co][ci].
// ---------------------------------------------------------------------------
__global__ void prep_kernel(const float* __restrict__ s0, const float* __restrict__ s1,
                            int coT, int ciT, int taps, int sel)
{
    const int idx = blockIdx.x * 256 + threadIdx.x;
    const int total = taps * coT * ciT;
    if (idx >= total) return;
    const int ci = idx % ciT;
    const int co = (idx / ciT) % coT;
    const int tap = idx / (ciT * coT);
    const float* s = s0;
    int c = co;
    if (s1 != nullptr && co >= 128) { s = s1; c = co - 128; }
    const float v = s[((size_t)c * ciT + ci) * taps + tap];
    pickW(sel)[idx] = __float2half_rn(v);
}

// ---------------------------------------------------------------------------
// Activation prep: fp32 NCHW (virtual concat, optional fused BN+ReLU) ->
// fp16 NHWC [b][pix][C]. Tile = 64 pixels x 64 channels with smem transpose.
// ---------------------------------------------------------------------------
__global__ __launch_bounds__(256)
void actprep_kernel(int inASel, const float* __restrict__ inAExt,
                    const float* __restrict__ inB,
                    int strA, int strB, int split, int C, int HW,
                    int useBn, int ssSel, int dstSel)
{
    __shared__ __half s_t[64][72];
    const int tid = threadIdx.x;
    const int pix0 = blockIdx.x * 64;
    const int c0   = blockIdx.y * 64;
    const int b    = blockIdx.z;
    const float* inA = (inASel < 0) ? inAExt : pickBuf(inASel);
    const float* ss  = pickSS(ssSel);
    __half* dst = pickAct(dstSel);

    const int cSub = tid >> 6, pixL = tid & 63;
#pragma unroll 4
    for (int ci = 0; ci < 16; ci++) {
        const int cl = ci * 4 + cSub;
        const int c = c0 + cl;
        float v;
        if (c < split) {
            v = inA[((size_t)(b * strA + c)) * HW + pix0 + pixL];
            if (useBn) v = fmaxf(fmaf(v, ss[2 * c], ss[2 * c + 1]), 0.f);
        } else {
            v = inB[((size_t)(b * strB + (c - split))) * HW + pix0 + pixL];
        }
        s_t[pixL][cl] = __float2half_rn(v);
    }
    __syncthreads();
    // write-out: 8 chunks (64 ch) x 32 pixels x 2 halves = full 64x64 tile
    const int chunk = tid & 7, pL0 = tid >> 3;
#pragma unroll
    for (int h = 0; h < 2; h++) {
        const int pL = pL0 + h * 32;
        const uint4 vh = *(const uint4*)&s_t[pL][chunk * 8];
        const size_t doff = (size_t)(b * HW + pix0 + pL) * C + c0 + chunk * 8;
        *(uint4*)(dst + doff) = vh;
    }
}

// ---------------------------------------------------------------------------
// conv-as-tap-GEMM via mma.sync fp16 (single pass, fp32 accum).
// D[128 co][128 sp] per CTA, 8 warps 4(M)x2(N). 3-stage cp.async pipeline
// (depth-2 prefetch), one barrier per iteration, 2 CTAs/SM.
// ---------------------------------------------------------------------------
__global__ __launch_bounds__(256, 2)
void conv_mma_kernel(
    int actSel, int C, int sH, int sW,
    int wSel, int coT,
    int tapSet, int tapCount,
    int outSel, int outBStride,
    int oyMul, int oyAdd, int oxMul, int oxAdd,
    int outW)
{
    extern __shared__ __align__(128) char smem[];
    const uint32_t sb = smem_u32(smem);
    int* s_bt = (int*)(smem + OFF_SB);
    int* s_yt = (int*)(smem + OFF_SY);
    int* s_xt = (int*)(smem + OFF_SX);

    const int tid = threadIdx.x;
    const int lane = tid & 31, wid = tid >> 5;
    const int wm = wid >> 1, wn = wid & 1;
    const int inHW = sH * sW;
    const int outHW = HWP;
    const int chanOff = blockIdx.y * 128;

    float* outP = pickBuf(outSel);
    const __half* act = pickAct(actSel);
    const __half* wgt = pickW(wSel);

    if (tid < 128) {
        const int s = blockIdx.x * 128 + tid;
        const int b = s / inHW; const int r = s - b * inHW;
        const int y = r / sW;
        s_bt[tid] = b; s_yt[tid] = y; s_xt[tid] = r - y * sW;
    }
    __syncthreads();

    // staging mapping: 2 threads per row, 4 x 16B chunks each (A and B alike)
    const int rowS = tid >> 1, partS = tid & 1;
    const int bS = s_bt[rowS], yS = s_yt[rowS], xS = s_xt[rowS];
    const uint32_t bDst0 = sb + OFF_STAGE + STG_B + rowS * 128;
    const uint32_t aDst0 = sb + OFF_STAGE + STG_A + rowS * 128;
    const int swzS = rowS & 7;
    const size_t wRowBase = (size_t)(chanOff + rowS) * C;

    float acc[2][8][4];
#pragma unroll
    for (int i = 0; i < 2; i++)
#pragma unroll
        for (int j = 0; j < 8; j++)
#pragma unroll
            for (int k = 0; k < 4; k++) acc[i][j][k] = 0.f;

    // ldmatrix lane addressing (XOR swizzle on 128B rows)
    const int sx = lane & 7;
    const uint32_t aRowBase = (uint32_t)(wm * 32 + (lane & 15)) * 128;
    const uint32_t bRowBase = (uint32_t)(wn * 64 + (lane & 7) + ((lane >> 4) << 3)) * 128;
    const int ka0 = lane >> 4;
    const int kb0 = (lane >> 3) & 1;

    const int nIter = (C >> 6) * tapCount;

    // ---- staging issue for iteration `it` into stage buffer `s` (0..2) ----
    auto stage = [&](int it, int s) {
        const int cbi = it / tapCount;
        const int t   = it - cbi * tapCount;
        const int cb  = cbi << 6;
        const int dy = c_dy[tapSet][t], dx = c_dx[tapSet][t], wi = c_wi[tapSet][t];
        const uint32_t sOff = (uint32_t)s * STAGE_BYTES;
        // B: fp16 activation row for pixel rowS shifted by tap
        {
            const int yy = yS + dy, xx = xS + dx;
            const bool inb = ((unsigned)yy < (unsigned)sH) && ((unsigned)xx < (unsigned)sW);
            const __half* src = inb
                ? act + (size_t)(bS * inHW + yy * sW + xx) * C + cb
                : act;
            const uint32_t sz = inb ? 16u : 0u;
            const uint32_t d = bDst0 + sOff;
#pragma unroll
            for (int j = 0; j < 4; j++) {
                const int c8 = partS * 4 + j;
                cp16(d + ((c8 ^ swzS) << 4), src + c8 * 8, sz);
            }
        }
        // A: weight row (co = rowS) for this tap
        {
            const __half* src = wgt + (size_t)wi * coT * C + wRowBase + cb;
            const uint32_t d = aDst0 + sOff;
#pragma unroll
            for (int j = 0; j < 4; j++) {
                const int c8 = partS * 4 + j;
                cp16(d + ((c8 ^ swzS) << 4), src + c8 * 8, 16u);
            }
        }
    };

    // prologue: stage iters 0 and 1 (nIter >= 16 always, >= 2 required)
    stage(0, 0); cp_commit();
    stage(1, 1); cp_commit();

    int st = 0;          // it % 3
    int st2 = 2;         // (it+2) % 3
    for (int it = 0; it < nIter; it++) {
        cp_wait1();          // group `it` complete (group it+1 still in flight)
        __syncthreads();     // data visible; all warps done with MMA(it-1)

        // depth-2 prefetch into buffer (it+2)%3 (last read by MMA(it-1))
        if (it + 2 < nIter) stage(it + 2, st2);
        cp_commit();         // possibly-empty group keeps the count uniform

        const uint32_t stBase = sb + OFF_STAGE + (uint32_t)st * STAGE_BYTES;
        const uint32_t Abase = stBase + STG_A;
        const uint32_t Bbase = stBase + STG_B;
#pragma unroll
        for (int k = 0; k < 4; k++) {
            const uint32_t aOff = (uint32_t)(((ka0 + 2 * k) ^ sx) << 4);
            const uint32_t bOff = (uint32_t)(((kb0 + 2 * k) ^ sx) << 4);
            uint32_t a0[4], a1[4];
            ldsm_x4(a0, Abase + aRowBase + aOff);
            ldsm_x4(a1, Abase + aRowBase + 16 * 128 + aOff);
#pragma unroll
            for (int tt = 0; tt < 4; tt++) {
                uint32_t bb[4];
                ldsm_x4(bb, Bbase + bRowBase + tt * 2048 + bOff);
                mma_f16(acc[0][tt*2  ], a0, bb);
                mma_f16(acc[0][tt*2+1], a0, bb + 2);
                mma_f16(acc[1][tt*2  ], a1, bb);
                mma_f16(acc[1][tt*2+1], a1, bb + 2);
            }
        }
        st  = (st  == 2) ? 0 : st  + 1;
        st2 = (st2 == 2) ? 0 : st2 + 1;
    }

    // ---- epilogue: registers -> global (fp32 NCHW scratch) ----
    uint32_t off[16];
#pragma unroll
    for (int i = 0; i < 16; i++) {
        const int nf = i >> 1, e = i & 1;
        const int spi = wn * 64 + nf * 8 + (lane & 3) * 2 + e;
        const int b = s_bt[spi];
        const int oy = s_yt[spi] * oyMul + oyAdd;
        const int ox = s_xt[spi] * oxMul + oxAdd;
        off[i] = (uint32_t)(b * outBStride) * (uint32_t)outHW
               + (uint32_t)(oy * outW + ox);
    }
    const int coBase = chanOff + wm * 32 + (lane >> 2);
#pragma unroll
    for (int mi = 0; mi < 2; mi++) {
        const size_t cOff0 = (size_t)(coBase + mi * 16) * outHW;
        const size_t cOff8 = cOff0 + (size_t)8 * outHW;
#pragma unroll
        for (int nf = 0; nf < 8; nf++) {
            outP[cOff0 + off[nf*2  ]] = acc[mi][nf][0];
            outP[cOff0 + off[nf*2+1]] = acc[mi][nf][1];
            outP[cOff8 + off[nf*2  ]] = acc[mi][nf][2];
            outP[cOff8 + off[nf*2+1]] = acc[mi][nf][3];
        }
    }
}

// ---------------------------------------------------------------------------
// Per-channel batch stats -> (scale, shift). Deterministic tree reduction.
// ---------------------------------------------------------------------------
__global__ void stats_kernel(int bufSel, int bStride, int chanOff,
                             const float* __restrict__ gamma,
                             const float* __restrict__ beta,
                             int ssSel)
{
    const float* buf = pickBuf(bufSel);
    float* ss = pickSS(ssSel);
    const int c = blockIdx.x;
    const int tid = threadIdx.x;
    float s = 0.f, q = 0.f;
    for (int b = 0; b < BB; b++) {
        const float4* p = (const float4*)(buf + (size_t)(b * bStride + chanOff + c) * HWP);
        for (int i = tid; i < HWP / 4; i += 256) {
            float4 v = p[i];
            s += v.x + v.y + v.z + v.w;
            q += v.x * v.x + v.y * v.y + v.z * v.z + v.w * v.w;
        }
    }
    __shared__ float red[512];
    red[tid] = s; red[256 + tid] = q;
    __syncthreads();
    for (int off = 128; off > 0; off >>= 1) {
        if (tid < off) {
            red[tid]       += red[tid + off];
            red[256 + tid] += red[256 + tid + off];
        }
        __syncthreads();
    }
    if (tid == 0) {
        const float N = (float)(BB * HWP);
        float mean = red[0] / N;
        float var  = red[256] / N - mean * mean;
        float inv  = rsqrtf(var + 1e-5f);
        float scv  = gamma[c] * inv;
        ss[2 * c]     = scv;
        ss[2 * c + 1] = beta[c] - mean * scv;
    }
}

// out = relu(bn(y2) + bn(ysc))
__global__ void final_kernel(float* __restrict__ out)
{
    const int t  = blockIdx.x * 256 + threadIdx.x;
    const int p  = t % 4800;
    const int bc = t / 4800;
    const int b = bc >> 7, c = bc & 127;
    const float s2  = g_ss2[2 * c],  t2  = g_ss2[2 * c + 1];
    const float ssc = g_ssSC[2 * c], tsc = g_ssSC[2 * c + 1];
    const float4 a = ((const float4*)(g_y2   + (size_t)(b * 128 + c) * HWP))[p];
    const float4 d = ((const float4*)(g_ybig + (size_t)(b * 256 + 128 + c) * HWP))[p];
    float4 o;
    o.x = fmaxf(fmaf(a.x, s2, t2) + fmaf(d.x, ssc, tsc), 0.f);
    o.y = fmaxf(fmaf(a.y, s2, t2) + fmaf(d.y, ssc, tsc), 0.f);
    o.z = fmaxf(fmaf(a.z, s2, t2) + fmaf(d.z, ssc, tsc), 0.f);
    o.w = fmaxf(fmaf(a.w, s2, t2) + fmaf(d.w, ssc, tsc), 0.f);
    ((float4*)out)[t] = o;
}

// ---------------------------------------------------------------------------
extern "C" void kernel_launch(void* const* d_in, const int* in_sizes, int n_in,
                              void* d_out, int out_size)
{
    const float* x    = (const float*)d_in[0];
    const float* side = (const float*)d_in[1];
    const float* w1   = (const float*)d_in[2];
    const float* g1   = (const float*)d_in[3];
    const float* b1   = (const float*)d_in[4];
    const float* w11  = (const float*)d_in[5];
    const float* g11  = (const float*)d_in[6];
    const float* b11  = (const float*)d_in[7];
    const float* w2   = (const float*)d_in[8];
    const float* g2   = (const float*)d_in[9];
    const float* b2   = (const float*)d_in[10];
    const float* wsc  = (const float*)d_in[11];
    const float* gsc  = (const float*)d_in[12];
    const float* bsc  = (const float*)d_in[13];
    float* out = (float*)d_out;

    cudaFuncSetAttribute(conv_mma_kernel,
                         cudaFuncAttributeMaxDynamicSharedMemorySize, SMEM_BYTES);

    // 0) weights -> fp16 [tap][co][ci]
    prep_kernel<<<(25*256*256 + 255)/256, 256>>>(w1, wsc, 256, 256, 25, 0);
    prep_kernel<<<( 9*128*256 + 255)/256, 256>>>(w11, nullptr, 128, 256, 9, 1);
    prep_kernel<<<( 9*128*128 + 255)/256, 256>>>(w2,  nullptr, 128, 128, 9, 2);

    // 0b) x -> fp16 NHWC
    {
        dim3 g(4800/64, 256/64, BB);
        actprep_kernel<<<g, 256>>>(-1, x, nullptr, CIN, 0, CIN, 256, 4800, 0, 0, 0);
    }

    // 1) sparse 5x5 conv (w1 -> ch 0..127, wsc -> ch 128..255 of g_ybig),
    //    4 parity launches over the 60x80 quad grid.
    dim3 gA(300, 2);
    const int cnt[5] = {9, 9, 6, 6, 4};
    const int pys[5] = {0, 0, 0, 1, 1};
    const int pxs[5] = {0, 0, 1, 0, 1};
    for (int set = 1; set <= 4; set++) {
        conv_mma_kernel<<<gA, 256, SMEM_BYTES>>>(
            /*actSel*/0, 256, 60, 80,
            /*wSel*/0, /*coT*/256, set, cnt[set],
            /*outSel*/0, 256,
            2, pys[set], 2, pxs[set], 160);
    }

    // 2) BN stats for both halves of g_ybig
    stats_kernel<<<128, 256>>>(0, 256, 0,   g1,  b1,  0);
    stats_kernel<<<128, 256>>>(0, 256, 128, gsc, bsc, 1);

    // 2b) concat input: bn+relu(y1) ch 0..127, side ch 128..255 -> fp16 NHWC
    {
        dim3 g(19200/64, 256/64, BB);
        actprep_kernel<<<g, 256>>>(0, nullptr, side, 256, 128, 128, 256, 19200, 1, 0, 1);
    }

    // 3) conv3x3 over concat -> y11
    dim3 g3(1200, 1);
    conv_mma_kernel<<<g3, 256, SMEM_BYTES>>>(
        /*actSel*/1, 256, 120, 160,
        /*wSel*/1, /*coT*/128, 0, 9,
        /*outSel*/1, 128,
        1, 0, 1, 0, 160);

    // 4) BN stats on y11; a11 = relu(bn(y11)) -> fp16 NHWC
    stats_kernel<<<128, 256>>>(1, 128, 0, g11, b11, 2);
    {
        dim3 g(19200/64, 128/64, BB);
        actprep_kernel<<<g, 256>>>(1, nullptr, nullptr, 128, 0, 128, 128, 19200, 1, 2, 2);
    }

    // 5) conv3x3 (Cin=128) -> y2
    conv_mma_kernel<<<g3, 256, SMEM_BYTES>>>(
        /*actSel*/2, 128, 120, 160,
        /*wSel*/2, /*coT*/128, 0, 9,
        /*outSel*/2, 128,
        1, 0, 1, 0, 160);

    // 6) BN stats for y2; final fuse: relu(bn(y2) + bn(ysc))
    stats_kernel<<<128, 256>>>(2, 128, 0, g2, b2, 3);
    final_kernel<<<19200, 256>>>(out);
}

// round 13
// speedup vs baseline: 8.2381x; 1.1900x over previous
#include <cuda_runtime.h>
#include <cuda_fp16.h>
#include <cstdint>
#include <cstddef>

#define BB   8
#define CIN  256
#define HWP  (120*160)   /* 19200 output plane size */
#define NSLOT 1200       /* partial-stats slots per channel (all convs) */

// ---------------- scratch (static device globals; no allocation) ----------------
__device__ float g_ybig[(size_t)BB * 256 * HWP]; // ch 0..127 conv1 raw, 128..255 shortcut raw
__device__ float g_y11 [(size_t)BB * 128 * HWP];
__device__ float g_y2  [(size_t)BB * 128 * HWP];
__device__ float g_ssA [256];   // (scale,shift) interleaved
__device__ float g_ssSC[256];
__device__ float g_ss11[256];
__device__ float g_ss2 [256];

// per-(channel, CTA-slot) partial sums for BN stats (written by conv epilogue)
__device__ float g_psum[256 * NSLOT];
__device__ float g_psq [256 * NSLOT];

// fp16 weights: [tap][co][ci]
__device__ __half g_wA [25 * 256 * 256];
__device__ __half g_w11[ 9 * 128 * 256];
__device__ __half g_w2 [ 9 * 128 * 128];

// fp16 activations, NHWC [b][pix][c]
__device__ __half g_xa [(size_t)BB *  4800 * 256];
__device__ __half g_cat[(size_t)BB * 19200 * 256];
__device__ __half g_a11[(size_t)BB * 19200 * 128];

__device__ __forceinline__ float* pickBuf(int s) {
    return s == 0 ? g_ybig : (s == 1 ? g_y11 : g_y2);
}
__device__ __forceinline__ float* pickSS(int s) {
    return s == 0 ? g_ssA : (s == 1 ? g_ssSC : (s == 2 ? g_ss11 : g_ss2));
}
__device__ __forceinline__ __half* pickW(int s) {
    return s == 0 ? g_wA : (s == 1 ? g_w11 : g_w2);
}
__device__ __forceinline__ __half* pickAct(int s) {
    return s == 0 ? g_xa : (s == 1 ? g_cat : g_a11);
}

// ---------------- tap tables ----------------
// set0: 3x3 conv (9 taps). sets 1-4: parity decompositions of the sparse-upsample
// 5x5 conv; parity (py,px): set1=(0,0) 9, set2=(0,1) 6, set3=(1,0) 6, set4=(1,1) 4.
__constant__ int c_dy[5][9] = {
    {-1,-1,-1, 0,0,0, 1,1,1},
    {-1,-1,-1, 0,0,0, 1,1,1},
    {-1,-1, 0,0, 1,1, 0,0,0},
    { 0, 0, 0, 1,1,1, 0,0,0},
    { 0, 0, 1, 1, 0,0,0,0,0},
};
__constant__ int c_dx[5][9] = {
    {-1,0,1, -1,0,1, -1,0,1},
    {-1,0,1, -1,0,1, -1,0,1},
    { 0,1, 0,1, 0,1, 0,0,0},
    {-1,0,1, -1,0,1, 0,0,0},
    { 0,1, 0,1, 0,0,0,0,0},
};
__constant__ int c_wi[5][9] = {
    {0,1,2, 3,4,5, 6,7,8},
    {0,2,4, 10,12,14, 20,22,24},
    {1,3, 11,13, 21,23, 0,0,0},
    {5,7,9, 15,17,19, 0,0,0},
    {6,8, 16,18, 0,0,0,0,0},
};
// per-parity-set (multiSet convA launch): tap count and output parity offsets
__constant__ int c_cntz[4] = {9, 6, 6, 4};
__constant__ int c_pyz [4] = {0, 0, 1, 1};
__constant__ int c_pxz [4] = {0, 1, 0, 1};

// ---------------- PTX helpers (sm_80+ baseline — compiles at sm_100) ----------------
__device__ __forceinline__ uint32_t smem_u32(const void* p) {
    uint32_t a;
    asm("{ .reg .u64 t; cvta.to.shared.u64 t, %1; cvt.u32.u64 %0, t; }" : "=r"(a) : "l"(p));
    return a;
}
__device__ __forceinline__ void ldsm_x4(uint32_t* r, uint32_t addr) {
    asm volatile("ldmatrix.sync.aligned.m8n8.x4.shared.b16 {%0,%1,%2,%3}, [%4];"
                 : "=r"(r[0]), "=r"(r[1]), "=r"(r[2]), "=r"(r[3]) : "r"(addr));
}
__device__ __forceinline__ void mma_f16(float* d, const uint32_t* a, const uint32_t* b) {
    asm volatile("mma.sync.aligned.m16n8k16.row.col.f32.f16.f16.f32 "
                 "{%0,%1,%2,%3},{%4,%5,%6,%7},{%8,%9},{%0,%1,%2,%3};"
                 : "+f"(d[0]), "+f"(d[1]), "+f"(d[2]), "+f"(d[3])
                 : "r"(a[0]), "r"(a[1]), "r"(a[2]), "r"(a[3]), "r"(b[0]), "r"(b[1]));
}
__device__ __forceinline__ void cp16(uint32_t dst, const void* src, uint32_t sz) {
    asm volatile("cp.async.cg.shared.global [%0], [%1], 16, %2;"
                 :: "r"(dst), "l"(src), "r"(sz) : "memory");
}
__device__ __forceinline__ void cp_commit() {
    asm volatile("cp.async.commit_group;" ::: "memory");
}
__device__ __forceinline__ void cp_wait1() {
    asm volatile("cp.async.wait_group 1;" ::: "memory");
}

// ---------------- SMEM layout: header + 3 pipeline stages (32KB each) ----------------
#define OFF_SB    0                    /* int[128] */
#define OFF_SY    512
#define OFF_SX    1024
#define OFF_STAGE 2048
#define STG_A     0                    /* 128co x 64ci fp16 = 16KB */
#define STG_B     16384                /* 128sp x 64ci fp16 = 16KB */
#define STAGE_BYTES 32768
#define NSTAGE    3
#define SMEM_BYTES (OFF_STAGE + NSTAGE * STAGE_BYTES)   /* 100352 -> 2 CTAs/SM */

// ---------------------------------------------------------------------------
// Weight prep: fp32 [co][ci][taps] (optionally two 128-co halves) ->
// fp16 [tap][co][ci].
// ---------------------------------------------------------------------------
__global__ void prep_kernel(const float* __restrict__ s0, const float* __restrict__ s1,
                            int coT, int ciT, int taps, int sel)
{
    const int idx = blockIdx.x * 256 + threadIdx.x;
    const int total = taps * coT * ciT;
    if (idx >= total) return;
    const int ci = idx % ciT;
    const int co = (idx / ciT) % coT;
    const int tap = idx / (ciT * coT);
    const float* s = s0;
    int c = co;
    if (s1 != nullptr && co >= 128) { s = s1; c = co - 128; }
    const float v = s[((size_t)c * ciT + ci) * taps + tap];
    pickW(sel)[idx] = __float2half_rn(v);
}

// ---------------------------------------------------------------------------
// Activation prep: fp32 NCHW (virtual concat, optional fused BN+ReLU) ->
// fp16 NHWC [b][pix][C]. Tile = 64 pixels x 64 channels with smem transpose.
// ---------------------------------------------------------------------------
__global__ __launch_bounds__(256)
void actprep_kernel(int inASel, const float* __restrict__ inAExt,
                    const float* __restrict__ inB,
                    int strA, int strB, int split, int C, int HW,
                    int useBn, int ssSel, int dstSel)
{
    __shared__ __half s_t[64][72];
    const int tid = threadIdx.x;
    const int pix0 = blockIdx.x * 64;
    const int c0   = blockIdx.y * 64;
    const int b    = blockIdx.z;
    const float* inA = (inASel < 0) ? inAExt : pickBuf(inASel);
    const float* ss  = pickSS(ssSel);
    __half* dst = pickAct(dstSel);

    const int cSub = tid >> 6, pixL = tid & 63;
#pragma unroll 4
    for (int ci = 0; ci < 16; ci++) {
        const int cl = ci * 4 + cSub;
        const int c = c0 + cl;
        float v;
        if (c < split) {
            v = inA[((size_t)(b * strA + c)) * HW + pix0 + pixL];
            if (useBn) v = fmaxf(fmaf(v, ss[2 * c], ss[2 * c + 1]), 0.f);
        } else {
            v = inB[((size_t)(b * strB + (c - split))) * HW + pix0 + pixL];
        }
        s_t[pixL][cl] = __float2half_rn(v);
    }
    __syncthreads();
    // write-out: 8 chunks (64 ch) x 32 pixels x 2 halves = full 64x64 tile
    const int chunk = tid & 7, pL0 = tid >> 3;
#pragma unroll
    for (int h = 0; h < 2; h++) {
        const int pL = pL0 + h * 32;
        const uint4 vh = *(const uint4*)&s_t[pL][chunk * 8];
        const size_t doff = (size_t)(b * HW + pix0 + pL) * C + c0 + chunk * 8;
        *(uint4*)(dst + doff) = vh;
    }
}

// ---------------------------------------------------------------------------
// conv-as-tap-GEMM via mma.sync fp16 (single pass, fp32 accum).
// D[128 co][128 sp] per CTA, 8 warps 4(M)x2(N). 3-stage cp.async pipeline
// (depth-2 prefetch), one barrier per iteration, 2 CTAs/SM.
// B fragments double-buffered (ldsm for tt+1 issued before MMAs of tt).
// Epilogue also emits deterministic per-(co,CTA) sum/sumsq partials for BN.
// multiSet=1: blockIdx.z selects parity set 1..4 (fused convA launch).
// ---------------------------------------------------------------------------
__global__ __launch_bounds__(256, 2)
void conv_mma_kernel(
    int actSel, int C, int sH, int sW,
    int wSel, int coT,
    int multiSet, int tapSet, int tapCount,
    int outSel, int outBStride,
    int oyMul, int oyAdd, int oxMul, int oxAdd,
    int outW)
{
    extern __shared__ __align__(128) char smem[];
    const uint32_t sb = smem_u32(smem);
    int* s_bt = (int*)(smem + OFF_SB);
    int* s_yt = (int*)(smem + OFF_SY);
    int* s_xt = (int*)(smem + OFF_SX);

    const int tid = threadIdx.x;
    const int lane = tid & 31, wid = tid >> 5;
    const int wm = wid >> 1, wn = wid & 1;
    const int inHW = sH * sW;
    const int outHW = HWP;
    const int chanOff = blockIdx.y * 128;

    // per-parity-set parameters (fused convA launch)
    int tapSetL = tapSet, tapCountL = tapCount, oyAddL = oyAdd, oxAddL = oxAdd;
    if (multiSet) {
        const int z = blockIdx.z;
        tapSetL = z + 1;
        tapCountL = c_cntz[z];
        oyAddL = c_pyz[z];
        oxAddL = c_pxz[z];
    }
    const int slot = blockIdx.z * gridDim.x + blockIdx.x;   // 0..1199

    float* outP = pickBuf(outSel);
    const __half* act = pickAct(actSel);
    const __half* wgt = pickW(wSel);

    if (tid < 128) {
        const int s = blockIdx.x * 128 + tid;
        const int b = s / inHW; const int r = s - b * inHW;
        const int y = r / sW;
        s_bt[tid] = b; s_yt[tid] = y; s_xt[tid] = r - y * sW;
    }
    __syncthreads();

    // staging mapping: 2 threads per row, 4 x 16B chunks each (A and B alike)
    const int rowS = tid >> 1, partS = tid & 1;
    const int bS = s_bt[rowS], yS = s_yt[rowS], xS = s_xt[rowS];
    const uint32_t bDst0 = sb + OFF_STAGE + STG_B + rowS * 128;
    const uint32_t aDst0 = sb + OFF_STAGE + STG_A + rowS * 128;
    const int swzS = rowS & 7;
    const size_t wRowBase = (size_t)(chanOff + rowS) * C;

    float acc[2][8][4];
#pragma unroll
    for (int i = 0; i < 2; i++)
#pragma unroll
        for (int j = 0; j < 8; j++)
#pragma unroll
            for (int k = 0; k < 4; k++) acc[i][j][k] = 0.f;

    // ldmatrix lane addressing (XOR swizzle on 128B rows)
    const int sx = lane & 7;
    const uint32_t aRowBase = (uint32_t)(wm * 32 + (lane & 15)) * 128;
    const uint32_t bRowBase = (uint32_t)(wn * 64 + (lane & 7) + ((lane >> 4) << 3)) * 128;
    const int ka0 = lane >> 4;
    const int kb0 = (lane >> 3) & 1;

    const int nIter = (C >> 6) * tapCountL;

    // ---- staging issue for iteration `it` into stage buffer `s` (0..2) ----
    auto stage = [&](int it, int s) {
        const int cbi = it / tapCountL;
        const int t   = it - cbi * tapCountL;
        const int cb  = cbi << 6;
        const int dy = c_dy[tapSetL][t], dx = c_dx[tapSetL][t], wi = c_wi[tapSetL][t];
        const uint32_t sOff = (uint32_t)s * STAGE_BYTES;
        // B: fp16 activation row for pixel rowS shifted by tap
        {
            const int yy = yS + dy, xx = xS + dx;
            const bool inb = ((unsigned)yy < (unsigned)sH) && ((unsigned)xx < (unsigned)sW);
            const __half* src = inb
                ? act + (size_t)(bS * inHW + yy * sW + xx) * C + cb
                : act;
            const uint32_t sz = inb ? 16u : 0u;
            const uint32_t d = bDst0 + sOff;
#pragma unroll
            for (int j = 0; j < 4; j++) {
                const int c8 = partS * 4 + j;
                cp16(d + ((c8 ^ swzS) << 4), src + c8 * 8, sz);
            }
        }
        // A: weight row (co = rowS) for this tap
        {
            const __half* src = wgt + (size_t)wi * coT * C + wRowBase + cb;
            const uint32_t d = aDst0 + sOff;
#pragma unroll
            for (int j = 0; j < 4; j++) {
                const int c8 = partS * 4 + j;
                cp16(d + ((c8 ^ swzS) << 4), src + c8 * 8, 16u);
            }
        }
    };

    // prologue: stage iters 0 and 1 (nIter >= 16 always, >= 2 required)
    stage(0, 0); cp_commit();
    stage(1, 1); cp_commit();

    int st = 0;          // it % 3
    int st2 = 2;         // (it+2) % 3
    for (int it = 0; it < nIter; it++) {
        cp_wait1();          // group `it` complete (group it+1 still in flight)
        __syncthreads();     // data visible; all warps done with MMA(it-1)

        // depth-2 prefetch into buffer (it+2)%3 (last read by MMA(it-1))
        if (it + 2 < nIter) stage(it + 2, st2);
        cp_commit();         // possibly-empty group keeps the count uniform

        const uint32_t stBase = sb + OFF_STAGE + (uint32_t)st * STAGE_BYTES;
        const uint32_t Abase = stBase + STG_A;
        const uint32_t Bbase = stBase + STG_B;
#pragma unroll
        for (int k = 0; k < 4; k++) {
            const uint32_t aOff = (uint32_t)(((ka0 + 2 * k) ^ sx) << 4);
            const uint32_t bOff = (uint32_t)(((kb0 + 2 * k) ^ sx) << 4);
            uint32_t a0[4], a1[4], bb[2][4];
            ldsm_x4(a0, Abase + aRowBase + aOff);
            ldsm_x4(a1, Abase + aRowBase + 16 * 128 + aOff);
            ldsm_x4(bb[0], Bbase + bRowBase + bOff);
#pragma unroll
            for (int tt = 0; tt < 4; tt++) {
                if (tt < 3)
                    ldsm_x4(bb[(tt + 1) & 1], Bbase + bRowBase + (tt + 1) * 2048 + bOff);
                const uint32_t* b = bb[tt & 1];
                mma_f16(acc[0][tt*2  ], a0, b);
                mma_f16(acc[0][tt*2+1], a0, b + 2);
                mma_f16(acc[1][tt*2  ], a1, b);
                mma_f16(acc[1][tt*2+1], a1, b + 2);
            }
        }
        st  = (st  == 2) ? 0 : st  + 1;
        st2 = (st2 == 2) ? 0 : st2 + 1;
    }

    // ---- epilogue: registers -> global (fp32 NCHW scratch) ----
    uint32_t off[16];
#pragma unroll
    for (int i = 0; i < 16; i++) {
        const int nf = i >> 1, e = i & 1;
        const int spi = wn * 64 + nf * 8 + (lane & 3) * 2 + e;
        const int b = s_bt[spi];
        const int oy = s_yt[spi] * oyMul + oyAddL;
        const int ox = s_xt[spi] * oxMul + oxAddL;
        off[i] = (uint32_t)(b * outBStride) * (uint32_t)outHW
               + (uint32_t)(oy * outW + ox);
    }
    const int coBase = chanOff + wm * 32 + (lane >> 2);
#pragma unroll
    for (int mi = 0; mi < 2; mi++) {
        const size_t cOff0 = (size_t)(coBase + mi * 16) * outHW;
        const size_t cOff8 = cOff0 + (size_t)8 * outHW;
#pragma unroll
        for (int nf = 0; nf < 8; nf++) {
            outP[cOff0 + off[nf*2  ]] = acc[mi][nf][0];
            outP[cOff0 + off[nf*2+1]] = acc[mi][nf][1];
            outP[cOff8 + off[nf*2  ]] = acc[mi][nf][2];
            outP[cOff8 + off[nf*2+1]] = acc[mi][nf][3];
        }
    }

    // ---- deterministic per-(co, CTA) BN partials: sum & sumsq ----
    // ps/pq index = mi*2 + h; h=0 -> co = base+mi*16, h=1 -> co = base+mi*16+8
    float ps[4], pq[4];
#pragma unroll
    for (int mi = 0; mi < 2; mi++)
#pragma unroll
        for (int h = 0; h < 2; h++) {
            float s = 0.f, q = 0.f;
#pragma unroll
            for (int nf = 0; nf < 8; nf++)
#pragma unroll
                for (int e = 0; e < 2; e++) {
                    const float v = acc[mi][nf][h * 2 + e];
                    s += v; q += v * v;
                }
            ps[mi * 2 + h] = s; pq[mi * 2 + h] = q;
        }
    // reduce over the 4 lanes sharing the same co (lane&3 spatial split)
#pragma unroll
    for (int i = 0; i < 4; i++) {
        ps[i] += __shfl_xor_sync(0xffffffffu, ps[i], 1);
        ps[i] += __shfl_xor_sync(0xffffffffu, ps[i], 2);
        pq[i] += __shfl_xor_sync(0xffffffffu, pq[i], 1);
        pq[i] += __shfl_xor_sync(0xffffffffu, pq[i], 2);
    }
    __syncthreads();    // mainloop smem reads done; reuse stage 0 as scratch
    float* sred = (float*)(smem + OFF_STAGE);          // [2][128]
    float* qred = (float*)(smem + OFF_STAGE + 1024);   // [2][128]
    if ((lane & 3) == 0) {
        const int l4 = lane >> 2;
#pragma unroll
        for (int mi = 0; mi < 2; mi++)
#pragma unroll
            for (int h = 0; h < 2; h++) {
                const int col = wm * 32 + l4 + mi * 16 + h * 8;
                sred[wn * 128 + col] = ps[mi * 2 + h];
                qred[wn * 128 + col] = pq[mi * 2 + h];
            }
    }
    __syncthreads();
    if (tid < 128) {
        const float s = sred[tid] + sred[128 + tid];
        const float q = qred[tid] + qred[128 + tid];
        g_psum[(size_t)(chanOff + tid) * NSLOT + slot] = s;
        g_psq [(size_t)(chanOff + tid) * NSLOT + slot] = q;
    }
}

// ---------------------------------------------------------------------------
// Combine per-CTA partials -> (scale, shift). One block per channel.
// Deterministic (fixed slot partition + tree reduction).
// ---------------------------------------------------------------------------
__global__ void combine_kernel(int chanOff,
                               const float* __restrict__ gamma,
                               const float* __restrict__ beta,
                               int ssSel)
{
    float* ss = pickSS(ssSel);
    const int c = blockIdx.x;
    const int tid = threadIdx.x;
    const float* psp = g_psum + (size_t)(chanOff + c) * NSLOT;
    const float* pqp = g_psq  + (size_t)(chanOff + c) * NSLOT;
    float s = 0.f, q = 0.f;
    for (int i = tid; i < NSLOT; i += 256) { s += psp[i]; q += pqp[i]; }
    __shared__ float red[512];
    red[tid] = s; red[256 + tid] = q;
    __syncthreads();
    for (int off = 128; off > 0; off >>= 1) {
        if (tid < off) {
            red[tid]       += red[tid + off];
            red[256 + tid] += red[256 + tid + off];
        }
        __syncthreads();
    }
    if (tid == 0) {
        const float N = (float)(BB * HWP);
        float mean = red[0] / N;
        float var  = red[256] / N - mean * mean;
        float inv  = rsqrtf(var + 1e-5f);
        float scv  = gamma[c] * inv;
        ss[2 * c]     = scv;
        ss[2 * c + 1] = beta[c] - mean * scv;
    }
}

// out = relu(bn(y2) + bn(ysc))
__global__ void final_kernel(float* __restrict__ out)
{
    const int t  = blockIdx.x * 256 + threadIdx.x;
    const int p  = t % 4800;
    const int bc = t / 4800;
    const int b = bc >> 7, c = bc & 127;
    const float s2  = g_ss2[2 * c],  t2  = g_ss2[2 * c + 1];
    const float ssc = g_ssSC[2 * c], tsc = g_ssSC[2 * c + 1];
    const float4 a = ((const float4*)(g_y2   + (size_t)(b * 128 + c) * HWP))[p];
    const float4 d = ((const float4*)(g_ybig + (size_t)(b * 256 + 128 + c) * HWP))[p];
    float4 o;
    o.x = fmaxf(fmaf(a.x, s2, t2) + fmaf(d.x, ssc, tsc), 0.f);
    o.y = fmaxf(fmaf(a.y, s2, t2) + fmaf(d.y, ssc, tsc), 0.f);
    o.z = fmaxf(fmaf(a.z, s2, t2) + fmaf(d.z, ssc, tsc), 0.f);
    o.w = fmaxf(fmaf(a.w, s2, t2) + fmaf(d.w, ssc, tsc), 0.f);
    ((float4*)out)[t] = o;
}

// ---------------------------------------------------------------------------
extern "C" void kernel_launch(void* const* d_in, const int* in_sizes, int n_in,
                              void* d_out, int out_size)
{
    const float* x    = (const float*)d_in[0];
    const float* side = (const float*)d_in[1];
    const float* w1   = (const float*)d_in[2];
    const float* g1   = (const float*)d_in[3];
    const float* b1   = (const float*)d_in[4];
    const float* w11  = (const float*)d_in[5];
    const float* g11  = (const float*)d_in[6];
    const float* b11  = (const float*)d_in[7];
    const float* w2   = (const float*)d_in[8];
    const float* g2   = (const float*)d_in[9];
    const float* b2   = (const float*)d_in[10];
    const float* wsc  = (const float*)d_in[11];
    const float* gsc  = (const float*)d_in[12];
    const float* bsc  = (const float*)d_in[13];
    float* out = (float*)d_out;

    cudaFuncSetAttribute(conv_mma_kernel,
                         cudaFuncAttributeMaxDynamicSharedMemorySize, SMEM_BYTES);

    // 0) weights -> fp16 [tap][co][ci]
    prep_kernel<<<(25*256*256 + 255)/256, 256>>>(w1, wsc, 256, 256, 25, 0);
    prep_kernel<<<( 9*128*256 + 255)/256, 256>>>(w11, nullptr, 128, 256, 9, 1);
    prep_kernel<<<( 9*128*128 + 255)/256, 256>>>(w2,  nullptr, 128, 128, 9, 2);

    // 0b) x -> fp16 NHWC
    {
        dim3 g(4800/64, 256/64, BB);
        actprep_kernel<<<g, 256>>>(-1, x, nullptr, CIN, 0, CIN, 256, 4800, 0, 0, 0);
    }

    // 1) sparse 5x5 conv, all 4 parity sets in ONE launch (z = set-1).
    {
        dim3 gA(300, 2, 4);
        conv_mma_kernel<<<gA, 256, SMEM_BYTES>>>(
            /*actSel*/0, 256, 60, 80,
            /*wSel*/0, /*coT*/256, /*multiSet*/1, 0, 0,
            /*outSel*/0, 256,
            2, 0, 2, 0, 160);
    }

    // 2) BN stats from conv partials (both halves)
    combine_kernel<<<128, 256>>>(0,   g1,  b1,  0);
    combine_kernel<<<128, 256>>>(128, gsc, bsc, 1);

    // 2b) concat input: bn+relu(y1) ch 0..127, side ch 128..255 -> fp16 NHWC
    {
        dim3 g(19200/64, 256/64, BB);
        actprep_kernel<<<g, 256>>>(0, nullptr, side, 256, 128, 128, 256, 19200, 1, 0, 1);
    }

    // 3) conv3x3 over concat -> y11
    dim3 g3(1200, 1, 1);
    conv_mma_kernel<<<g3, 256, SMEM_BYTES>>>(
        /*actSel*/1, 256, 120, 160,
        /*wSel*/1, /*coT*/128, /*multiSet*/0, 0, 9,
        /*outSel*/1, 128,
        1, 0, 1, 0, 160);

    // 4) BN stats on y11 from partials; a11 = relu(bn(y11)) -> fp16 NHWC
    combine_kernel<<<128, 256>>>(0, g11, b11, 2);
    {
        dim3 g(19200/64, 128/64, BB);
        actprep_kernel<<<g, 256>>>(1, nullptr, nullptr, 128, 0, 128, 128, 19200, 1, 2, 2);
    }

    // 5) conv3x3 (Cin=128) -> y2
    conv_mma_kernel<<<g3, 256, SMEM_BYTES>>>(
        /*actSel*/2, 128, 120, 160,
        /*wSel*/2, /*coT*/128, /*multiSet*/0, 0, 9,
        /*outSel*/2, 128,
        1, 0, 1, 0, 160);

    // 6) BN stats for y2 from partials; final fuse: relu(bn(y2) + bn(ysc))
    combine_kernel<<<128, 256>>>(0, g2, b2, 3);
    final_kernel<<<19200, 256>>>(out);
}